// round 8
// baseline (speedup 1.0000x reference)
#include <cuda_runtime.h>
#include <cuda_fp16.h>
#include <cstdint>
#include <cstddef>

#define HH 1024
#define TT 256
#define BB 64
#define BT (BB*TT)       /* 16384 */
#define G4 (4*HH)        /* 4096 */

/* fp16 GEMM tile constants (stride in halves) */
#define HSTR 40
#define L_ST (256*HSTR)             /* lstm1 stage halves (A128+B128) */
#define G_AT (128*HSTR)             /* gemm A region halves */
#define G_STG (384*HSTR)            /* gemm stage halves (A128+B256)  */

/* recurrence smem byte offsets (fragment-LDG edition) */
#define R3_WS_B   0                 /* Ws: 64*1032 halves = 132096 B  */
#define R3_PART_B 132096            /* part: 8*2112 f32 = 67584 B     */
#define R3_SMEM_B 199680
#define P2_STR 66
#define P2_SZ  (32*P2_STR)          /* 2112 floats per warp partial   */

/* fp16 scratch offsets (halves) */
#define X16_OFF  0u
#define W_L1A    4194304u
#define W_L1B    5242880u
#define W_L2A    9437184u
#define W_L2B    13631488u
#define W_M1     17825792u
#define W_M2     18874368u
#define W16_TOT  19398656u

// ------------------------- scratch (device globals) --------------------------
__device__ __align__(256) float  g_gates[(size_t)BT * G4];   // fp32 xg scratch
__device__ __align__(256) __half g_w16[W16_TOT];             // converted x + weights
__device__ __align__(256) __half g_h1[(size_t)BT * HH];
__device__ __align__(256) __half g_h2[(size_t)BT * HH];
__device__ __align__(256) __half g_hF[2 * 2 * 32768];        // [group][parity] fragment-layout h
__device__ __align__(256) __half g_z1[BB * HH];
__device__ __align__(256) __half g_z2[BB * (HH/2)];
__device__ volatile unsigned g_cnt2[2]   = {0, 0};
__device__ volatile unsigned g_sense2[2] = {0, 0};

// ------------------------- helpers ------------------------------------------
__device__ __forceinline__ uint32_t ld_u32h(const __half* p) {
    return *(const uint32_t*)p;
}
__device__ __forceinline__ void mma_fp16(float c[4],
                                         uint32_t a0, uint32_t a1, uint32_t a2, uint32_t a3,
                                         uint32_t b0, uint32_t b1) {
    asm volatile(
        "mma.sync.aligned.m16n8k16.row.col.f32.f16.f16.f32 "
        "{%0,%1,%2,%3}, {%4,%5,%6,%7}, {%8,%9}, {%0,%1,%2,%3};"
        : "+f"(c[0]), "+f"(c[1]), "+f"(c[2]), "+f"(c[3])
        : "r"(a0), "r"(a1), "r"(a2), "r"(a3), "r"(b0), "r"(b1));
}
__device__ __forceinline__ float sigf(float x) { return 1.0f / (1.0f + expf(-x)); }

__device__ __forceinline__ void cp16(uint32_t dsh, const void* src) {
    asm volatile("cp.async.cg.shared.global [%0], [%1], 16;" :: "r"(dsh), "l"(src));
}
__device__ __forceinline__ void cp_commit() { asm volatile("cp.async.commit_group;"); }

// =============================================================================
// fp32 -> fp16 conversion of xx + 6 weight matrices (one launch)
// =============================================================================
__global__ void convert_kernel(const float* __restrict__ xx,
                               const float* __restrict__ w0, const float* __restrict__ w1,
                               const float* __restrict__ w2, const float* __restrict__ w3,
                               const float* __restrict__ w4, const float* __restrict__ w5)
{
    const uint32_t i4 = blockIdx.x * blockDim.x + threadIdx.x;   // float4 index
    const float* src; uint32_t base4;
    if      (i4 < 1048576u) { src = xx; base4 = 0u; }
    else if (i4 < 1310720u) { src = w0; base4 = 1048576u; }
    else if (i4 < 2359296u) { src = w1; base4 = 1310720u; }
    else if (i4 < 3407872u) { src = w2; base4 = 2359296u; }
    else if (i4 < 4456448u) { src = w3; base4 = 3407872u; }
    else if (i4 < 4718592u) { src = w4; base4 = 4456448u; }
    else                    { src = w5; base4 = 4718592u; }
    const float4 v = ((const float4*)src)[i4 - base4];
    __half2* dst = (__half2*)(g_w16 + (size_t)i4 * 4);
    dst[0] = __floats2half2_rn(v.x, v.y);
    dst[1] = __floats2half2_rn(v.z, v.w);
}

// =============================================================================
// fp16 GEMM: C = A @ W^T (+bias, +ReLU). BM=128, BN=256, BK=32, 4-stage.
// =============================================================================
template<int RELU, int HOUT>
__launch_bounds__(256, 1)
__global__ void gemm16_kernel(const __half* __restrict__ A, long long asr,
                              const __half* __restrict__ W,
                              const float* __restrict__ b1p, const float* __restrict__ b2p,
                              void* __restrict__ Cv, int M, int N, int K)
{
    extern __shared__ __half smh[];
    const int tid = threadIdx.x, lane = tid & 31, warp = tid >> 5;
    const int wm = warp >> 2, wn = warp & 3;
    const int g = lane >> 2, q = lane & 3;
    const int mb = blockIdx.y * 128, nb = blockIdx.x * 256;

    float acc[4][8][4];
#pragma unroll
    for (int a = 0; a < 4; a++)
#pragma unroll
        for (int b = 0; b < 8; b++)
#pragma unroll
            for (int c = 0; c < 4; c++) acc[a][b][c] = 0.0f;

    const uint32_t smb = (uint32_t)__cvta_generic_to_shared(smh);
    const __half* aptr[2]; uint32_t adst[2];
#pragma unroll
    for (int i = 0; i < 2; i++) {
        const int slot = tid + i * 256;
        const int row = slot >> 2, kc = (slot & 3) * 8;
        int gr = mb + row; if (gr > M - 1) gr = M - 1;
        aptr[i] = A + (size_t)gr * asr + kc;
        adst[i] = smb + (uint32_t)((row * HSTR + kc) * 2);
    }
    const __half* bptr[4]; uint32_t bdst[4];
#pragma unroll
    for (int i = 0; i < 4; i++) {
        const int slot = tid + i * 256;
        const int row = slot >> 2, kc = (slot & 3) * 8;
        bptr[i] = W + (size_t)(nb + row) * K + kc;
        bdst[i] = smb + (uint32_t)((G_AT + row * HSTR + kc) * 2);
    }

    const int KT = K >> 5;
    auto issue = [&](int kt) {
        const uint32_t so = (uint32_t)((kt & 3) * G_STG * 2);
        const int koff = kt * 32;
#pragma unroll
        for (int i = 0; i < 2; i++) cp16(adst[i] + so, aptr[i] + koff);
#pragma unroll
        for (int i = 0; i < 4; i++) cp16(bdst[i] + so, bptr[i] + koff);
        cp_commit();
    };

    const int pre = KT < 3 ? KT : 3;
    for (int s = 0; s < pre; ++s) issue(s);

    for (int kt = 0; kt < KT; ++kt) {
        if (kt < KT - 2)       asm volatile("cp.async.wait_group 2;");
        else if (kt == KT - 2) asm volatile("cp.async.wait_group 1;");
        else                   asm volatile("cp.async.wait_group 0;");
        __syncthreads();
        if (kt + 3 < KT) issue(kt + 3);

        const __half* Ab = smh + (kt & 3) * G_STG;
        const __half* Bb = Ab + G_AT;
#pragma unroll
        for (int kk = 0; kk < 32; kk += 16) {
            uint32_t af[4][4], bfr[8][2];
#pragma unroll
            for (int mt = 0; mt < 4; mt++) {
                const int r = wm * 64 + mt * 16 + g;
                af[mt][0] = ld_u32h(Ab + r * HSTR + kk + 2 * q);
                af[mt][1] = ld_u32h(Ab + (r + 8) * HSTR + kk + 2 * q);
                af[mt][2] = ld_u32h(Ab + r * HSTR + kk + 2 * q + 8);
                af[mt][3] = ld_u32h(Ab + (r + 8) * HSTR + kk + 2 * q + 8);
            }
#pragma unroll
            for (int nt = 0; nt < 8; nt++) {
                const int n = wn * 64 + nt * 8 + g;
                bfr[nt][0] = ld_u32h(Bb + n * HSTR + kk + 2 * q);
                bfr[nt][1] = ld_u32h(Bb + n * HSTR + kk + 2 * q + 8);
            }
#pragma unroll
            for (int mt = 0; mt < 4; mt++)
#pragma unroll
                for (int nt = 0; nt < 8; nt++)
                    mma_fp16(acc[mt][nt], af[mt][0], af[mt][1], af[mt][2], af[mt][3],
                             bfr[nt][0], bfr[nt][1]);
        }
    }

#pragma unroll
    for (int mt = 0; mt < 4; mt++) {
#pragma unroll
        for (int nt = 0; nt < 8; nt++) {
            const int row0 = mb + wm * 64 + mt * 16 + g;
            const int col  = nb + wn * 64 + nt * 8 + 2 * q;
            const float b0v = (b1p ? b1p[col]     : 0.f) + (b2p ? b2p[col]     : 0.f);
            const float b1v = (b1p ? b1p[col + 1] : 0.f) + (b2p ? b2p[col + 1] : 0.f);
            float v0 = acc[mt][nt][0] + b0v, v1 = acc[mt][nt][1] + b1v;
            float v2 = acc[mt][nt][2] + b0v, v3 = acc[mt][nt][3] + b1v;
            if (RELU) {
                v0 = fmaxf(v0, 0.f); v1 = fmaxf(v1, 0.f);
                v2 = fmaxf(v2, 0.f); v3 = fmaxf(v3, 0.f);
            }
            if (HOUT) {
                __half* C = (__half*)Cv;
                if (row0 < M)     *(__half2*)(C + (size_t)row0 * N + col)       = __floats2half2_rn(v0, v1);
                if (row0 + 8 < M) *(__half2*)(C + (size_t)(row0 + 8) * N + col) = __floats2half2_rn(v2, v3);
            } else {
                float* C = (float*)Cv;
                if (row0 < M)     *(float2*)(C + (size_t)row0 * N + col)       = make_float2(v0, v1);
                if (row0 + 8 < M) *(float2*)(C + (size_t)(row0 + 8) * N + col) = make_float2(v2, v3);
            }
        }
    }
}

// =============================================================================
// fused lstm1 (fp16): h = sig(o)*tanh(sig(i)*tanh(g)); f gate skipped.
// =============================================================================
__launch_bounds__(256, 1)
__global__ void lstm1_16_kernel(const __half* __restrict__ A, long long asr,
                                const __half* __restrict__ W,
                                const float* __restrict__ bih, const float* __restrict__ bhh,
                                __half* __restrict__ Hout, int M, int K)
{
    extern __shared__ __half smh[];
    const int tid = threadIdx.x, lane = tid & 31, warp = tid >> 5;
    const int wm = warp >> 2, wn = warp & 3;
    const int g = lane >> 2, q = lane & 3;
    const int mb = blockIdx.y * 128, nb = blockIdx.x * 128;

    const uint32_t smb = (uint32_t)__cvta_generic_to_shared(smh);

    const __half* aptr[2]; uint32_t adst[2];
#pragma unroll
    for (int i = 0; i < 2; i++) {
        const int slot = tid + i * 256;
        const int row = slot >> 2, kc = (slot & 3) * 8;
        int gr = mb + row; if (gr > M - 1) gr = M - 1;
        aptr[i] = A + (size_t)gr * asr + kc;
        adst[i] = smb + (uint32_t)((row * HSTR + kc) * 2);
    }
    uint32_t bdst[2]; int brow[2], bkc[2];
#pragma unroll
    for (int i = 0; i < 2; i++) {
        const int slot = tid + i * 256;
        brow[i] = slot >> 2; bkc[i] = (slot & 3) * 8;
        bdst[i] = smb + (uint32_t)(((128 + brow[i]) * HSTR + bkc[i]) * 2);
    }

    const int KT = K >> 5;
    float keep[4][4][4];
    const int gset[3] = {0, 2, 3};

#pragma unroll 1
    for (int ph = 0; ph < 3; ++ph) {
        const int gate = gset[ph];
        const __half* Wb = W + ((size_t)(gate * HH + nb)) * K;

        float acc[4][4][4];
#pragma unroll
        for (int a = 0; a < 4; a++)
#pragma unroll
            for (int b = 0; b < 4; b++)
#pragma unroll
                for (int c = 0; c < 4; c++) acc[a][b][c] = 0.0f;

        auto issue = [&](int kt) {
            const int koff = kt * 32;
            const uint32_t so = (uint32_t)((kt & 3) * L_ST * 2);
#pragma unroll
            for (int i = 0; i < 2; i++) cp16(adst[i] + so, aptr[i] + koff);
#pragma unroll
            for (int i = 0; i < 2; i++) cp16(bdst[i] + so, Wb + (size_t)brow[i] * K + bkc[i] + koff);
            cp_commit();
        };

        const int pre = KT < 3 ? KT : 3;
        for (int s = 0; s < pre; ++s) issue(s);

        for (int kt = 0; kt < KT; ++kt) {
            if (kt < KT - 2)       asm volatile("cp.async.wait_group 2;");
            else if (kt == KT - 2) asm volatile("cp.async.wait_group 1;");
            else                   asm volatile("cp.async.wait_group 0;");
            __syncthreads();
            if (kt + 3 < KT) issue(kt + 3);

            const __half* Ab = smh + (kt & 3) * L_ST;
            const __half* Bb = Ab + 128 * HSTR;
#pragma unroll
            for (int kk = 0; kk < 32; kk += 16) {
                uint32_t af[4][4], bfr[4][2];
#pragma unroll
                for (int mt = 0; mt < 4; mt++) {
                    const int r = wm * 64 + mt * 16 + g;
                    af[mt][0] = ld_u32h(Ab + r * HSTR + kk + 2 * q);
                    af[mt][1] = ld_u32h(Ab + (r + 8) * HSTR + kk + 2 * q);
                    af[mt][2] = ld_u32h(Ab + r * HSTR + kk + 2 * q + 8);
                    af[mt][3] = ld_u32h(Ab + (r + 8) * HSTR + kk + 2 * q + 8);
                }
#pragma unroll
                for (int nt = 0; nt < 4; nt++) {
                    const int n = wn * 32 + nt * 8 + g;
                    bfr[nt][0] = ld_u32h(Bb + n * HSTR + kk + 2 * q);
                    bfr[nt][1] = ld_u32h(Bb + n * HSTR + kk + 2 * q + 8);
                }
#pragma unroll
                for (int mt = 0; mt < 4; mt++)
#pragma unroll
                    for (int nt = 0; nt < 4; nt++)
                        mma_fp16(acc[mt][nt], af[mt][0], af[mt][1], af[mt][2], af[mt][3],
                                 bfr[nt][0], bfr[nt][1]);
            }
        }
        __syncthreads();

#pragma unroll
        for (int mt = 0; mt < 4; mt++) {
#pragma unroll
            for (int nt = 0; nt < 4; nt++) {
                const int gcol = gate * HH + nb + wn * 32 + nt * 8 + 2 * q;
                const float b0 = bih[gcol] + bhh[gcol];
                const float b1 = bih[gcol + 1] + bhh[gcol + 1];
                if (ph == 0) {
                    keep[mt][nt][0] = sigf(acc[mt][nt][0] + b0);
                    keep[mt][nt][1] = sigf(acc[mt][nt][1] + b1);
                    keep[mt][nt][2] = sigf(acc[mt][nt][2] + b0);
                    keep[mt][nt][3] = sigf(acc[mt][nt][3] + b1);
                } else if (ph == 1) {
                    keep[mt][nt][0] *= tanhf(acc[mt][nt][0] + b0);
                    keep[mt][nt][1] *= tanhf(acc[mt][nt][1] + b1);
                    keep[mt][nt][2] *= tanhf(acc[mt][nt][2] + b0);
                    keep[mt][nt][3] *= tanhf(acc[mt][nt][3] + b1);
                } else {
                    const int row0 = mb + wm * 64 + mt * 16 + g;
                    const int colh = nb + wn * 32 + nt * 8 + 2 * q;
                    const float v0 = sigf(acc[mt][nt][0] + b0) * tanhf(keep[mt][nt][0]);
                    const float v1 = sigf(acc[mt][nt][1] + b1) * tanhf(keep[mt][nt][1]);
                    const float v2 = sigf(acc[mt][nt][2] + b0) * tanhf(keep[mt][nt][2]);
                    const float v3 = sigf(acc[mt][nt][3] + b1) * tanhf(keep[mt][nt][3]);
                    if (row0 < M)     *(__half2*)(Hout + (size_t)row0 * HH + colh)       = __floats2half2_rn(v0, v1);
                    if (row0 + 8 < M) *(__half2*)(Hout + (size_t)(row0 + 8) * HH + colh) = __floats2half2_rn(v2, v3);
                }
            }
        }
    }
}

// ------------------------- per-group barrier (64 CTAs) ------------------------
__device__ __forceinline__ void group_bar(int G)
{
    __threadfence();
    __syncthreads();
    if (threadIdx.x == 0) {
        const unsigned gen = g_sense2[G];
        const unsigned arrived = atomicAdd((unsigned*)&g_cnt2[G], 1u);
        if (arrived == 63u) {
            g_cnt2[G] = 0;
            __threadfence();
            atomicAdd((unsigned*)&g_sense2[G], 1u);
        } else {
            while (g_sense2[G] == gen) { __nanosleep(16); }
        }
        __threadfence();
    }
    __syncthreads();
}

// =============================================================================
// RECURRENT LSTM LAYER — fragment-layout LDG edition
//
// 2 groups x 64 CTAs; group G owns batch rows [G*32, +32). CTA owns 16 h cols
// (64 gate cols); Whh slab 128 KB fp16 in SMEM. h is stored in GLOBAL memory
// in exact mma-fragment order: halves addr = ((wk*8+kk)*32 + lane)*16 +
// (mt*4 + rbit + 2*hi)*2 + (k&1). Per step each warp issues 16 ld.global.cg
// v4 loads (no TMA, no mbar, no staging SMEM). 8-way K-split, fp32 partials
// in a DEDICATED smem region (one syncthreads per step + group barrier).
// =============================================================================
__launch_bounds__(256, 1)
__global__ void recur16_kernel(const float* __restrict__ xg,   // [BT, 4096] fp32
                               const float* __restrict__ Whh,  // [4096, 1024] fp32
                               __half* __restrict__ hs,        // [BT, 1024]
                               __half* __restrict__ hF,        // [2G][2p][32768] fragments
                               int write_all)
{
    extern __shared__ char smc[];
    __half* Ws  = (__half*)(smc + R3_WS_B);    // [64][1032]
    float* part = (float*)(smc + R3_PART_B);   // 8 x [32][66] f32 (dedicated)

    const int tid = threadIdx.x, lane = tid & 31;
    const int wk = tid >> 5;                 // K-split warp index 0..7
    const int g = lane >> 2, q = lane & 3;
    const int G  = blockIdx.x >> 6;
    const int cg = blockIdx.x & 63;
    const int n0h = cg * 16;

    // Whh slab fp16: packed row c = gate*16 + j  <-  Whh[gate*HH + n0h + j]
#pragma unroll 1
    for (int c = 0; c < 64; c++) {
        const int row = (c >> 4) * HH + n0h + (c & 15);
        const float4 v = *(const float4*)(Whh + (size_t)row * HH + tid * 4);
        __half* d = Ws + c * 1032 + tid * 4;
        d[0] = __float2half_rn(v.x); d[1] = __float2half_rn(v.y);
        d[2] = __float2half_rn(v.z); d[3] = __float2half_rn(v.w);
    }
    __syncthreads();

    __half* hFg = hF + G * 65536;            // this group's [2][32768]

    // reader: warp wk, kk -> float4 index ((wk*8+kk)*32 + lane)*2 (+0/+1)
    const int rd_base = (wk * 8) * 32 + lane;   // *2 for float4 units, +kk*32

    // writer mapping: thread owns (r0, k_own) and (r1, k_own)
    const int j = tid & 15, r0 = tid >> 4, r1 = r0 + 16;
    const int brow0 = G * 32 + r0, brow1 = G * 32 + r1;
    const int k_own = n0h + j;
    const int wkw = k_own >> 7, kkw = (k_own >> 4) & 7;
    const int kw = k_own & 15, hi = kw >> 3, qw = (kw & 7) >> 1, hsel = k_own & 1;
    const int seg_base = ((wkw * 8 + kkw) * 32) * 16;
    auto frag_off = [&](int r) {
        const int lane_w = 4 * (r & 7) + qw;
        const int s = (r >> 4) * 4 + ((r >> 3) & 1) + 2 * hi;
        return seg_base + lane_w * 16 + s * 2 + hsel;
    };
    const int off0 = frag_off(r0), off1 = frag_off(r1);

    float cs0 = 0.f, cs1 = 0.f;

    for (int t = 0; t < TT; t++) {
        // xg prefetch (DRAM, long latency; consumed at step end)
        const size_t x0 = ((size_t)(brow0 * TT + t)) * G4 + k_own;
        const size_t x1 = ((size_t)(brow1 * TT + t)) * G4 + k_own;
        const float xi0 = xg[x0], xf0 = xg[x0 + 1024], xgg0 = xg[x0 + 2048], xo0 = xg[x0 + 3072];
        const float xi1 = xg[x1], xf1 = xg[x1 + 1024], xgg1 = xg[x1 + 2048], xo1 = xg[x1 + 3072];

        if (t > 0) {
            const float4* hsrc = (const float4*)(hFg + (size_t)(t & 1) * 32768);

            float acc[2][8][4];
#pragma unroll
            for (int a = 0; a < 2; a++)
#pragma unroll
                for (int b = 0; b < 8; b++)
#pragma unroll
                    for (int cc = 0; cc < 4; cc++) acc[a][b][cc] = 0.0f;

            // rolling 4-deep fragment prefetch (L1-bypassed: coherent via L2)
            float4 av0[4], av1[4];
#pragma unroll
            for (int p = 0; p < 4; p++) {
                av0[p] = __ldcg(hsrc + (rd_base + p * 32) * 2);
                av1[p] = __ldcg(hsrc + (rd_base + p * 32) * 2 + 1);
            }

#pragma unroll
            for (int kk = 0; kk < 8; ++kk) {
                const float4 f0 = av0[kk & 3], f1 = av1[kk & 3];
                if (kk + 4 < 8) {
                    av0[kk & 3] = __ldcg(hsrc + (rd_base + (kk + 4) * 32) * 2);
                    av1[kk & 3] = __ldcg(hsrc + (rd_base + (kk + 4) * 32) * 2 + 1);
                }
                uint32_t a[2][4];
                a[0][0] = __float_as_uint(f0.x); a[0][1] = __float_as_uint(f0.y);
                a[0][2] = __float_as_uint(f0.z); a[0][3] = __float_as_uint(f0.w);
                a[1][0] = __float_as_uint(f1.x); a[1][1] = __float_as_uint(f1.y);
                a[1][2] = __float_as_uint(f1.z); a[1][3] = __float_as_uint(f1.w);

                const int kglob = wk * 128 + kk * 16 + 2 * q;
                uint32_t bfr[8][2];
#pragma unroll
                for (int nt = 0; nt < 8; nt++) {
                    const int n = nt * 8 + g;
                    bfr[nt][0] = ld_u32h(Ws + n * 1032 + kglob);
                    bfr[nt][1] = ld_u32h(Ws + n * 1032 + kglob + 8);
                }
#pragma unroll
                for (int mt = 0; mt < 2; mt++)
#pragma unroll
                    for (int nt = 0; nt < 8; nt++)
                        mma_fp16(acc[mt][nt], a[mt][0], a[mt][1], a[mt][2], a[mt][3],
                                 bfr[nt][0], bfr[nt][1]);
            }

            // per-warp fp32 partials (dedicated region; prior reduce reads are
            // separated by the previous step's group barrier)
            float* pw = part + wk * P2_SZ;
#pragma unroll
            for (int mt = 0; mt < 2; mt++) {
#pragma unroll
                for (int nt = 0; nt < 8; nt++) {
                    const int r = mt * 16 + g;
                    const int cc = nt * 8 + 2 * q;
                    *(float2*)(pw + r * P2_STR + cc)       = make_float2(acc[mt][nt][0], acc[mt][nt][1]);
                    *(float2*)(pw + (r + 8) * P2_STR + cc) = make_float2(acc[mt][nt][2], acc[mt][nt][3]);
                }
            }
            __syncthreads();
        }

        float gi0 = xi0, gf0 = xf0, gg0 = xgg0, go0 = xo0;
        float gi1 = xi1, gf1 = xf1, gg1 = xgg1, go1 = xo1;
        if (t > 0) {
#pragma unroll
            for (int w = 0; w < 8; w++) {
                const float* pw = part + w * P2_SZ;
                gi0 += pw[r0 * P2_STR + j];      gf0 += pw[r0 * P2_STR + 16 + j];
                gg0 += pw[r0 * P2_STR + 32 + j]; go0 += pw[r0 * P2_STR + 48 + j];
                gi1 += pw[r1 * P2_STR + j];      gf1 += pw[r1 * P2_STR + 16 + j];
                gg1 += pw[r1 * P2_STR + 32 + j]; go1 += pw[r1 * P2_STR + 48 + j];
            }
        }
        cs0 = sigf(gf0) * cs0 + sigf(gi0) * tanhf(gg0);
        cs1 = sigf(gf1) * cs1 + sigf(gi1) * tanhf(gg1);
        const float h0v = sigf(go0) * tanhf(cs0);
        const float h1v = sigf(go1) * tanhf(cs1);

        // store h in fragment layout for next step's direct LDG
        __half* hdst = hFg + (size_t)((t + 1) & 1) * 32768;
        hdst[off0] = __float2half_rn(h0v);
        hdst[off1] = __float2half_rn(h1v);
        if (write_all || t == TT - 1) {
            hs[((size_t)(brow0 * TT + t)) * HH + k_own] = __float2half_rn(h0v);
            hs[((size_t)(brow1 * TT + t)) * HH + k_own] = __float2half_rn(h1v);
        }

        if (t < TT - 1) group_bar(G);
    }
}

// ------------------------- final MLP layer 3 ---------------------------------
__global__ void mlp3_kernel(const __half* __restrict__ z2, const float* __restrict__ W3,
                            const float* __restrict__ b3, float* __restrict__ out)
{
    __shared__ float red[8];
    const int b = blockIdx.x;
    float s = 0.f;
    for (int k = threadIdx.x; k < 512; k += 256)
        s += __half2float(z2[b * 512 + k]) * W3[k];
#pragma unroll
    for (int o = 16; o; o >>= 1) s += __shfl_down_sync(0xffffffffu, s, o);
    if ((threadIdx.x & 31) == 0) red[threadIdx.x >> 5] = s;
    __syncthreads();
    if (threadIdx.x < 8) {
        s = red[threadIdx.x];
#pragma unroll
        for (int o = 4; o; o >>= 1) s += __shfl_down_sync(0xffu, s, o);
        if (threadIdx.x == 0) out[b] = s + b3[0];
    }
}

// ------------------------- launcher ------------------------------------------
extern "C" void kernel_launch(void* const* d_in, const int* in_sizes, int n_in,
                              void* d_out, int out_size)
{
    const float* xx       = (const float*)d_in[0];
    const float* l1_Wih0  = (const float*)d_in[1];
    const float* l1_bih0  = (const float*)d_in[2];
    const float* l1_bhh0  = (const float*)d_in[3];
    const float* l1_Wih1  = (const float*)d_in[4];
    const float* l1_bih1  = (const float*)d_in[5];
    const float* l1_bhh1  = (const float*)d_in[6];
    const float* l2_Wih0  = (const float*)d_in[7];
    const float* l2_Whh0  = (const float*)d_in[8];
    const float* l2_bih0  = (const float*)d_in[9];
    const float* l2_bhh0  = (const float*)d_in[10];
    const float* l2_Wih1  = (const float*)d_in[11];
    const float* l2_Whh1  = (const float*)d_in[12];
    const float* l2_bih1  = (const float*)d_in[13];
    const float* l2_bhh1  = (const float*)d_in[14];
    const float* mlp_W1   = (const float*)d_in[15];
    const float* mlp_b1   = (const float*)d_in[16];
    const float* mlp_W2   = (const float*)d_in[17];
    const float* mlp_b2   = (const float*)d_in[18];
    const float* mlp_W3   = (const float*)d_in[19];
    const float* mlp_b3   = (const float*)d_in[20];
    float* out = (float*)d_out;

    void* p;
    cudaGetSymbolAddress(&p, g_gates); float*  gates = (float*)p;
    cudaGetSymbolAddress(&p, g_w16);   __half* w16   = (__half*)p;
    cudaGetSymbolAddress(&p, g_h1);    __half* h1    = (__half*)p;
    cudaGetSymbolAddress(&p, g_h2);    __half* h2    = (__half*)p;
    cudaGetSymbolAddress(&p, g_hF);    __half* hF    = (__half*)p;
    cudaGetSymbolAddress(&p, g_z1);    __half* z1    = (__half*)p;
    cudaGetSymbolAddress(&p, g_z2);    __half* z2    = (__half*)p;

    const int lstm1_smem = 4 * L_ST * 2;     // 81920 B
    const int gemm_smem  = 4 * G_STG * 2;    // 122880 B
    const int recur_smem = R3_SMEM_B;        // 199680 B
    cudaFuncSetAttribute((const void*)gemm16_kernel<0,0>, cudaFuncAttributeMaxDynamicSharedMemorySize, gemm_smem);
    cudaFuncSetAttribute((const void*)gemm16_kernel<1,1>, cudaFuncAttributeMaxDynamicSharedMemorySize, gemm_smem);
    cudaFuncSetAttribute((const void*)lstm1_16_kernel,    cudaFuncAttributeMaxDynamicSharedMemorySize, lstm1_smem);
    cudaFuncSetAttribute((const void*)recur16_kernel,     cudaFuncAttributeMaxDynamicSharedMemorySize, recur_smem);

    const dim3 blk(256);

    // [0] fp32 -> fp16 (xx + 6 weight matrices)
    convert_kernel<<<4849664 / 256, blk>>>(xx, l1_Wih0, l1_Wih1, l2_Wih0, l2_Wih1, mlp_W1, mlp_W2);

    // [1][2] lstm1 (fused, f gate skipped)
    lstm1_16_kernel<<<dim3(HH / 128, BT / 128), blk, lstm1_smem>>>(w16 + X16_OFF, 256, w16 + W_L1A,
                                                                   l1_bih0, l1_bhh0, h1, BT, 256);
    lstm1_16_kernel<<<dim3(HH / 128, BT / 128), blk, lstm1_smem>>>(h1, HH, w16 + W_L1B,
                                                                   l1_bih1, l1_bhh1, h2, BT, HH);

    // [3][4] lstm2 layer 0 xg (split) ; [5] recurrence (ncu -s 5 target)
    gemm16_kernel<0,0><<<dim3(G4 / 256, 64), blk, gemm_smem>>>(h2, HH, w16 + W_L2A, l2_bih0, l2_bhh0,
                                                               gates, BT / 2, G4, HH);
    gemm16_kernel<0,0><<<dim3(G4 / 256, 64), blk, gemm_smem>>>(h2 + (size_t)(BT / 2) * HH, HH, w16 + W_L2A,
                                                               l2_bih0, l2_bhh0,
                                                               gates + (size_t)(BT / 2) * G4, BT / 2, G4, HH);
    recur16_kernel<<<128, blk, recur_smem>>>(gates, l2_Whh0, h1, hF, 1);

    // [6][7] lstm2 layer 1
    gemm16_kernel<0,0><<<dim3(G4 / 256, BT / 128), blk, gemm_smem>>>(h1, HH, w16 + W_L2B, l2_bih1, l2_bhh1,
                                                                     gates, BT, G4, HH);
    recur16_kernel<<<128, blk, recur_smem>>>(gates, l2_Whh1, h2, hF, 0);

    // [8][9][10] MLP
    gemm16_kernel<1,1><<<dim3(HH / 256, 1), blk, gemm_smem>>>(h2 + (size_t)(TT - 1) * HH, (long long)TT * HH,
                                                              w16 + W_M1, mlp_b1, nullptr, z1, BB, HH, HH);
    gemm16_kernel<1,1><<<dim3((HH / 2) / 256, 1), blk, gemm_smem>>>(z1, HH, w16 + W_M2, mlp_b2, nullptr,
                                                                    z2, BB, HH / 2, HH);
    mlp3_kernel<<<BB, blk>>>(z2, mlp_W3, mlp_b3, out);
}

// round 9
// speedup vs baseline: 1.0880x; 1.0880x over previous
#include <cuda_runtime.h>
#include <cuda_fp16.h>
#include <cstdint>
#include <cstddef>

#define HH 1024
#define TT 256
#define BB 64
#define BT (BB*TT)       /* 16384 */
#define G4 (4*HH)        /* 4096 */

/* fp16 GEMM tile constants (stride in halves) */
#define HSTR 40
#define L_ST (256*HSTR)             /* lstm1 stage halves (A128+B128) */
#define G_AT (128*HSTR)             /* gemm A region halves */
#define G_STG (384*HSTR)            /* gemm stage halves (A128+B256)  */

/* fused recurrence smem (bytes) */
#define FW_STR 1032                 /* slab row stride (halves)      */
#define F_G_B  (3*32*FW_STR*2)      /* 198144: gate region base      */
#define FG_STR 40                   /* gate buffer row stride (f32)  */
#define FG_SZ  (64*FG_STR*4)        /* 10240 B per gate buffer       */
#define F_SMEM_B (F_G_B + 3*FG_SZ)  /* 228864 B                      */

/* fp16 scratch offsets (halves) */
#define X16_OFF  0u
#define W_L1A    4194304u
#define W_L1B    5242880u
#define W_L2A    9437184u
#define W_L2B    13631488u
#define W_M1     17825792u
#define W_M2     18874368u
#define W16_TOT  19398656u

// ------------------------- scratch (device globals) --------------------------
__device__ __align__(256) float  g_gates[(size_t)BT * G4];   // fp32 xg1 scratch
__device__ __align__(256) __half g_w16[W16_TOT];             // converted x + weights
__device__ __align__(256) __half g_h1[(size_t)BT * HH];
__device__ __align__(256) __half g_h2[(size_t)BT * HH];
__device__ __align__(256) __half g_h1F[2 * 65536];           // h1 fragment buffer [parity]
__device__ __align__(256) __half g_h2F[2 * 65536];           // h2 fragment buffer [parity]
__device__ __align__(256) __half g_hlast[BB * HH];           // final h2(255) for MLP
__device__ __align__(256) __half g_z1[BB * HH];
__device__ __align__(256) __half g_z2[BB * (HH/2)];
__device__ volatile unsigned g_cnt = 0;
__device__ volatile unsigned g_sense = 0;

// ------------------------- helpers ------------------------------------------
__device__ __forceinline__ uint32_t ld_u32h(const __half* p) {
    return *(const uint32_t*)p;
}
__device__ __forceinline__ void mma_fp16(float c[4],
                                         uint32_t a0, uint32_t a1, uint32_t a2, uint32_t a3,
                                         uint32_t b0, uint32_t b1) {
    asm volatile(
        "mma.sync.aligned.m16n8k16.row.col.f32.f16.f16.f32 "
        "{%0,%1,%2,%3}, {%4,%5,%6,%7}, {%8,%9}, {%0,%1,%2,%3};"
        : "+f"(c[0]), "+f"(c[1]), "+f"(c[2]), "+f"(c[3])
        : "r"(a0), "r"(a1), "r"(a2), "r"(a3), "r"(b0), "r"(b1));
}
__device__ __forceinline__ float sigf(float x) { return 1.0f / (1.0f + expf(-x)); }

__device__ __forceinline__ void cp16(uint32_t dsh, const void* src) {
    asm volatile("cp.async.cg.shared.global [%0], [%1], 16;" :: "r"(dsh), "l"(src));
}
__device__ __forceinline__ void cp_commit() { asm volatile("cp.async.commit_group;"); }

// =============================================================================
// fp32 -> fp16 conversion of xx + 6 weight matrices (one launch)
// =============================================================================
__global__ void convert_kernel(const float* __restrict__ xx,
                               const float* __restrict__ w0, const float* __restrict__ w1,
                               const float* __restrict__ w2, const float* __restrict__ w3,
                               const float* __restrict__ w4, const float* __restrict__ w5)
{
    const uint32_t i4 = blockIdx.x * blockDim.x + threadIdx.x;   // float4 index
    const float* src; uint32_t base4;
    if      (i4 < 1048576u) { src = xx; base4 = 0u; }
    else if (i4 < 1310720u) { src = w0; base4 = 1048576u; }
    else if (i4 < 2359296u) { src = w1; base4 = 1310720u; }
    else if (i4 < 3407872u) { src = w2; base4 = 2359296u; }
    else if (i4 < 4456448u) { src = w3; base4 = 3407872u; }
    else if (i4 < 4718592u) { src = w4; base4 = 4456448u; }
    else                    { src = w5; base4 = 4718592u; }
    const float4 v = ((const float4*)src)[i4 - base4];
    __half2* dst = (__half2*)(g_w16 + (size_t)i4 * 4);
    dst[0] = __floats2half2_rn(v.x, v.y);
    dst[1] = __floats2half2_rn(v.z, v.w);
}

// =============================================================================
// fp16 GEMM: C = A @ W^T (+bias, +ReLU). BM=128, BN=256, BK=32, 4-stage.
// =============================================================================
template<int RELU, int HOUT>
__launch_bounds__(256, 1)
__global__ void gemm16_kernel(const __half* __restrict__ A, long long asr,
                              const __half* __restrict__ W,
                              const float* __restrict__ b1p, const float* __restrict__ b2p,
                              void* __restrict__ Cv, int M, int N, int K)
{
    extern __shared__ __half smh[];
    const int tid = threadIdx.x, lane = tid & 31, warp = tid >> 5;
    const int wm = warp >> 2, wn = warp & 3;
    const int g = lane >> 2, q = lane & 3;
    const int mb = blockIdx.y * 128, nb = blockIdx.x * 256;

    float acc[4][8][4];
#pragma unroll
    for (int a = 0; a < 4; a++)
#pragma unroll
        for (int b = 0; b < 8; b++)
#pragma unroll
            for (int c = 0; c < 4; c++) acc[a][b][c] = 0.0f;

    const uint32_t smb = (uint32_t)__cvta_generic_to_shared(smh);
    const __half* aptr[2]; uint32_t adst[2];
#pragma unroll
    for (int i = 0; i < 2; i++) {
        const int slot = tid + i * 256;
        const int row = slot >> 2, kc = (slot & 3) * 8;
        int gr = mb + row; if (gr > M - 1) gr = M - 1;
        aptr[i] = A + (size_t)gr * asr + kc;
        adst[i] = smb + (uint32_t)((row * HSTR + kc) * 2);
    }
    const __half* bptr[4]; uint32_t bdst[4];
#pragma unroll
    for (int i = 0; i < 4; i++) {
        const int slot = tid + i * 256;
        const int row = slot >> 2, kc = (slot & 3) * 8;
        bptr[i] = W + (size_t)(nb + row) * K + kc;
        bdst[i] = smb + (uint32_t)((G_AT + row * HSTR + kc) * 2);
    }

    const int KT = K >> 5;
    auto issue = [&](int kt) {
        const uint32_t so = (uint32_t)((kt & 3) * G_STG * 2);
        const int koff = kt * 32;
#pragma unroll
        for (int i = 0; i < 2; i++) cp16(adst[i] + so, aptr[i] + koff);
#pragma unroll
        for (int i = 0; i < 4; i++) cp16(bdst[i] + so, bptr[i] + koff);
        cp_commit();
    };

    const int pre = KT < 3 ? KT : 3;
    for (int s = 0; s < pre; ++s) issue(s);

    for (int kt = 0; kt < KT; ++kt) {
        if (kt < KT - 2)       asm volatile("cp.async.wait_group 2;");
        else if (kt == KT - 2) asm volatile("cp.async.wait_group 1;");
        else                   asm volatile("cp.async.wait_group 0;");
        __syncthreads();
        if (kt + 3 < KT) issue(kt + 3);

        const __half* Ab = smh + (kt & 3) * G_STG;
        const __half* Bb = Ab + G_AT;
#pragma unroll
        for (int kk = 0; kk < 32; kk += 16) {
            uint32_t af[4][4], bfr[8][2];
#pragma unroll
            for (int mt = 0; mt < 4; mt++) {
                const int r = wm * 64 + mt * 16 + g;
                af[mt][0] = ld_u32h(Ab + r * HSTR + kk + 2 * q);
                af[mt][1] = ld_u32h(Ab + (r + 8) * HSTR + kk + 2 * q);
                af[mt][2] = ld_u32h(Ab + r * HSTR + kk + 2 * q + 8);
                af[mt][3] = ld_u32h(Ab + (r + 8) * HSTR + kk + 2 * q + 8);
            }
#pragma unroll
            for (int nt = 0; nt < 8; nt++) {
                const int n = wn * 64 + nt * 8 + g;
                bfr[nt][0] = ld_u32h(Bb + n * HSTR + kk + 2 * q);
                bfr[nt][1] = ld_u32h(Bb + n * HSTR + kk + 2 * q + 8);
            }
#pragma unroll
            for (int mt = 0; mt < 4; mt++)
#pragma unroll
                for (int nt = 0; nt < 8; nt++)
                    mma_fp16(acc[mt][nt], af[mt][0], af[mt][1], af[mt][2], af[mt][3],
                             bfr[nt][0], bfr[nt][1]);
        }
    }

#pragma unroll
    for (int mt = 0; mt < 4; mt++) {
#pragma unroll
        for (int nt = 0; nt < 8; nt++) {
            const int row0 = mb + wm * 64 + mt * 16 + g;
            const int col  = nb + wn * 64 + nt * 8 + 2 * q;
            const float b0v = (b1p ? b1p[col]     : 0.f) + (b2p ? b2p[col]     : 0.f);
            const float b1v = (b1p ? b1p[col + 1] : 0.f) + (b2p ? b2p[col + 1] : 0.f);
            float v0 = acc[mt][nt][0] + b0v, v1 = acc[mt][nt][1] + b1v;
            float v2 = acc[mt][nt][2] + b0v, v3 = acc[mt][nt][3] + b1v;
            if (RELU) {
                v0 = fmaxf(v0, 0.f); v1 = fmaxf(v1, 0.f);
                v2 = fmaxf(v2, 0.f); v3 = fmaxf(v3, 0.f);
            }
            if (HOUT) {
                __half* C = (__half*)Cv;
                if (row0 < M)     *(__half2*)(C + (size_t)row0 * N + col)       = __floats2half2_rn(v0, v1);
                if (row0 + 8 < M) *(__half2*)(C + (size_t)(row0 + 8) * N + col) = __floats2half2_rn(v2, v3);
            } else {
                float* C = (float*)Cv;
                if (row0 < M)     *(float2*)(C + (size_t)row0 * N + col)       = make_float2(v0, v1);
                if (row0 + 8 < M) *(float2*)(C + (size_t)(row0 + 8) * N + col) = make_float2(v2, v3);
            }
        }
    }
}

// =============================================================================
// fused lstm1 (fp16): h = sig(o)*tanh(sig(i)*tanh(g)); f gate skipped.
// =============================================================================
__launch_bounds__(256, 1)
__global__ void lstm1_16_kernel(const __half* __restrict__ A, long long asr,
                                const __half* __restrict__ W,
                                const float* __restrict__ bih, const float* __restrict__ bhh,
                                __half* __restrict__ Hout, int M, int K)
{
    extern __shared__ __half smh[];
    const int tid = threadIdx.x, lane = tid & 31, warp = tid >> 5;
    const int wm = warp >> 2, wn = warp & 3;
    const int g = lane >> 2, q = lane & 3;
    const int mb = blockIdx.y * 128, nb = blockIdx.x * 128;

    const uint32_t smb = (uint32_t)__cvta_generic_to_shared(smh);

    const __half* aptr[2]; uint32_t adst[2];
#pragma unroll
    for (int i = 0; i < 2; i++) {
        const int slot = tid + i * 256;
        const int row = slot >> 2, kc = (slot & 3) * 8;
        int gr = mb + row; if (gr > M - 1) gr = M - 1;
        aptr[i] = A + (size_t)gr * asr + kc;
        adst[i] = smb + (uint32_t)((row * HSTR + kc) * 2);
    }
    uint32_t bdst[2]; int brow[2], bkc[2];
#pragma unroll
    for (int i = 0; i < 2; i++) {
        const int slot = tid + i * 256;
        brow[i] = slot >> 2; bkc[i] = (slot & 3) * 8;
        bdst[i] = smb + (uint32_t)(((128 + brow[i]) * HSTR + bkc[i]) * 2);
    }

    const int KT = K >> 5;
    float keep[4][4][4];
    const int gset[3] = {0, 2, 3};

#pragma unroll 1
    for (int ph = 0; ph < 3; ++ph) {
        const int gate = gset[ph];
        const __half* Wb = W + ((size_t)(gate * HH + nb)) * K;

        float acc[4][4][4];
#pragma unroll
        for (int a = 0; a < 4; a++)
#pragma unroll
            for (int b = 0; b < 4; b++)
#pragma unroll
                for (int c = 0; c < 4; c++) acc[a][b][c] = 0.0f;

        auto issue = [&](int kt) {
            const int koff = kt * 32;
            const uint32_t so = (uint32_t)((kt & 3) * L_ST * 2);
#pragma unroll
            for (int i = 0; i < 2; i++) cp16(adst[i] + so, aptr[i] + koff);
#pragma unroll
            for (int i = 0; i < 2; i++) cp16(bdst[i] + so, Wb + (size_t)brow[i] * K + bkc[i] + koff);
            cp_commit();
        };

        const int pre = KT < 3 ? KT : 3;
        for (int s = 0; s < pre; ++s) issue(s);

        for (int kt = 0; kt < KT; ++kt) {
            if (kt < KT - 2)       asm volatile("cp.async.wait_group 2;");
            else if (kt == KT - 2) asm volatile("cp.async.wait_group 1;");
            else                   asm volatile("cp.async.wait_group 0;");
            __syncthreads();
            if (kt + 3 < KT) issue(kt + 3);

            const __half* Ab = smh + (kt & 3) * L_ST;
            const __half* Bb = Ab + 128 * HSTR;
#pragma unroll
            for (int kk = 0; kk < 32; kk += 16) {
                uint32_t af[4][4], bfr[4][2];
#pragma unroll
                for (int mt = 0; mt < 4; mt++) {
                    const int r = wm * 64 + mt * 16 + g;
                    af[mt][0] = ld_u32h(Ab + r * HSTR + kk + 2 * q);
                    af[mt][1] = ld_u32h(Ab + (r + 8) * HSTR + kk + 2 * q);
                    af[mt][2] = ld_u32h(Ab + r * HSTR + kk + 2 * q + 8);
                    af[mt][3] = ld_u32h(Ab + (r + 8) * HSTR + kk + 2 * q + 8);
                }
#pragma unroll
                for (int nt = 0; nt < 4; nt++) {
                    const int n = wn * 32 + nt * 8 + g;
                    bfr[nt][0] = ld_u32h(Bb + n * HSTR + kk + 2 * q);
                    bfr[nt][1] = ld_u32h(Bb + n * HSTR + kk + 2 * q + 8);
                }
#pragma unroll
                for (int mt = 0; mt < 4; mt++)
#pragma unroll
                    for (int nt = 0; nt < 4; nt++)
                        mma_fp16(acc[mt][nt], af[mt][0], af[mt][1], af[mt][2], af[mt][3],
                                 bfr[nt][0], bfr[nt][1]);
            }
        }
        __syncthreads();

#pragma unroll
        for (int mt = 0; mt < 4; mt++) {
#pragma unroll
            for (int nt = 0; nt < 4; nt++) {
                const int gcol = gate * HH + nb + wn * 32 + nt * 8 + 2 * q;
                const float b0 = bih[gcol] + bhh[gcol];
                const float b1 = bih[gcol + 1] + bhh[gcol + 1];
                if (ph == 0) {
                    keep[mt][nt][0] = sigf(acc[mt][nt][0] + b0);
                    keep[mt][nt][1] = sigf(acc[mt][nt][1] + b1);
                    keep[mt][nt][2] = sigf(acc[mt][nt][2] + b0);
                    keep[mt][nt][3] = sigf(acc[mt][nt][3] + b1);
                } else if (ph == 1) {
                    keep[mt][nt][0] *= tanhf(acc[mt][nt][0] + b0);
                    keep[mt][nt][1] *= tanhf(acc[mt][nt][1] + b1);
                    keep[mt][nt][2] *= tanhf(acc[mt][nt][2] + b0);
                    keep[mt][nt][3] *= tanhf(acc[mt][nt][3] + b1);
                } else {
                    const int row0 = mb + wm * 64 + mt * 16 + g;
                    const int colh = nb + wn * 32 + nt * 8 + 2 * q;
                    const float v0 = sigf(acc[mt][nt][0] + b0) * tanhf(keep[mt][nt][0]);
                    const float v1 = sigf(acc[mt][nt][1] + b1) * tanhf(keep[mt][nt][1]);
                    const float v2 = sigf(acc[mt][nt][2] + b0) * tanhf(keep[mt][nt][2]);
                    const float v3 = sigf(acc[mt][nt][3] + b1) * tanhf(keep[mt][nt][3]);
                    if (row0 < M)     *(__half2*)(Hout + (size_t)row0 * HH + colh)       = __floats2half2_rn(v0, v1);
                    if (row0 + 8 < M) *(__half2*)(Hout + (size_t)(row0 + 8) * HH + colh) = __floats2half2_rn(v2, v3);
                }
            }
        }
    }
}

// ------------------------- 128-CTA grid barrier -------------------------------
__device__ __forceinline__ void grid_bar()
{
    __threadfence();
    __syncthreads();
    if (threadIdx.x == 0) {
        const unsigned gen = g_sense;
        const unsigned arrived = atomicAdd((unsigned*)&g_cnt, 1u);
        if (arrived == 127u) {
            g_cnt = 0;
            __threadfence();
            atomicAdd((unsigned*)&g_sense, 1u);
        } else {
            while (g_sense == gen) { __nanosleep(16); }
        }
        __threadfence();
    }
    __syncthreads();
}

// =============================================================================
// FUSED DUAL-LAYER RECURRENCE (lstm2 layer0 + layer1, software-pipelined)
//
// 128 CTAs x 256 thr; CTA owns 8 h cols for BOTH layers (32 gate cols each).
// SMEM: 3 fp16 weight slabs (Whh1, Wih2, Whh2; 32x1024 each, stride 1032) +
// 3 fp32 gate buffers [64][40]. h1/h2 live in global fragment-layout buffers.
// Pipeline step s (0..256): layer1 computes h1(s) from xg1(s) + h1(s-1)@Whh1;
// layer2 computes h2(s-1) from h1(s-1)@Wih2 + b2 + h2(s-2)@Whh2.
// Warps 0-3: L1 + I2 units (shared h1 A-fragments, M-split4, K-full);
// warps 4-7: H2 unit. One 128-CTA barrier per step.
// =============================================================================
__launch_bounds__(256, 1)
__global__ void fused_recur_kernel(const float* __restrict__ xg1,   // [BT,4096] f32
                                   const float* __restrict__ Whh1,  // [4096,1024] f32
                                   const float* __restrict__ Wih2,  // [4096,1024] f32
                                   const float* __restrict__ Whh2,  // [4096,1024] f32
                                   const float* __restrict__ b2i,
                                   const float* __restrict__ b2h,
                                   __half* __restrict__ hlast,      // [64,1024]
                                   __half* __restrict__ h1F,        // [2][65536]
                                   __half* __restrict__ h2F)        // [2][65536]
{
    extern __shared__ char smc[];
    __half* slab = (__half*)smc;                       // 3 x [32][1032]
    float*  L1g  = (float*)(smc + F_G_B);              // [64][40]
    float*  PIg  = (float*)(smc + F_G_B + FG_SZ);      // [64][40]
    float*  PHg  = (float*)(smc + F_G_B + 2 * FG_SZ);  // [64][40]

    const int tid = threadIdx.x, lane = tid & 31, warp = tid >> 5;
    const int g = lane >> 2, q = lane & 3;
    const int n0 = blockIdx.x * 8;

    // ---- load 3 weight slabs (fp16, conflict-free stride 1032) ----
#pragma unroll 1
    for (int c = 0; c < 96; c++) {
        const float* Wsrc = (c < 32) ? Whh1 : (c < 64) ? Wih2 : Whh2;
        const int rr = c & 31;
        const int row = (rr >> 3) * HH + n0 + (rr & 7);
        const float4 v = *(const float4*)(Wsrc + (size_t)row * HH + tid * 4);
        __half* d = slab + c * FW_STR + tid * 4;
        d[0] = __float2half_rn(v.x); d[1] = __float2half_rn(v.y);
        d[2] = __float2half_rn(v.z); d[3] = __float2half_rn(v.w);
    }
    __syncthreads();

    const __half* Ws1 = slab;
    const __half* Wi2 = slab + 32 * FW_STR;
    const __half* Ws2 = slab + 64 * FW_STR;

    // ---- mma role: warps 0-3 (L1+I2 on h1), warps 4-7 (H2 on h2) ----
    const int mq = warp & 3;            // M quarter (rows mq*16..mq*16+15)
    const int isL = (warp < 4);
    // B fragment pointers (per nt; index += kk*16, +8 for second half)
    const __half* bA[4]; const __half* bB[4];
#pragma unroll
    for (int nt = 0; nt < 4; nt++) {
        const int n = nt * 8 + g;
        bA[nt] = (isL ? Ws1 : Ws2) + n * FW_STR + 2 * q;
        bB[nt] = Wi2 + n * FW_STR + 2 * q;   // only used by warps 0-3
    }

    // ---- elementwise mapping: thread -> (r0, r1, col j) ----
    const int j = tid & 7, r0 = tid >> 3, r1 = r0 + 32;
    const int k_own = n0 + j;
    // fragment write offsets (same formula for h1F / h2F)
    const int kkw = k_own >> 4, kc = k_own & 15;
    const int lane_w = ((0) , 0);
    (void)lane_w;
    auto frag_off = [&](int r) {
        const int mqw = r >> 4, rr = r & 15;
        const int lw = (rr & 7) * 4 + ((kc & 7) >> 1);
        const int s2 = ((rr >= 8) ? 1 : 0) + ((kc >= 8) ? 2 : 0);
        return ((mqw * 64 + kkw) * 32 + lw) * 8 + s2 * 2 + (kc & 1);
    };
    const int off0 = frag_off(r0), off1 = frag_off(r1);

    // layer-2 per-column biases
    float bias2[4];
#pragma unroll
    for (int gg = 0; gg < 4; gg++)
        bias2[gg] = b2i[gg * HH + k_own] + b2h[gg * HH + k_own];

    float c1a = 0.f, c1b = 0.f, c2a = 0.f, c2b = 0.f;

#pragma unroll 1
    for (int s = 0; s <= TT; s++) {
        // xg1 prefetch for layer1 (valid s<=255)
        float xi0 = 0.f, xf0 = 0.f, xg0 = 0.f, xo0 = 0.f;
        float xi1 = 0.f, xf1 = 0.f, xg2_ = 0.f, xo1 = 0.f;
        if (s < TT) {
            const size_t x0 = ((size_t)(r0 * TT + s)) * G4 + k_own;
            const size_t x1 = ((size_t)(r1 * TT + s)) * G4 + k_own;
            xi0 = xg1[x0]; xf0 = xg1[x0 + 1024]; xg0 = xg1[x0 + 2048]; xo0 = xg1[x0 + 3072];
            xi1 = xg1[x1]; xf1 = xg1[x1 + 1024]; xg2_ = xg1[x1 + 2048]; xo1 = xg1[x1 + 3072];
        }

        // ---- mma phase ----
        const int par = (s - 1) & 1;
        const int doA = isL ? (s >= 1) : (s >= 2);   // L1/I2 need h1(s-1); H2 needs h2(s-2)
        if (doA) {
            const float4* Ab = (const float4*)((isL ? h1F : h2F) + (size_t)par * 65536)
                               + (size_t)mq * 64 * 32 + lane;

            float accA[4][4], accB[4][4];
#pragma unroll
            for (int nt = 0; nt < 4; nt++)
#pragma unroll
                for (int cc = 0; cc < 4; cc++) { accA[nt][cc] = 0.f; accB[nt][cc] = 0.f; }

            float4 buf[4];
#pragma unroll
            for (int p = 0; p < 4; p++) buf[p] = __ldcg(Ab + p * 32);

#pragma unroll 4
            for (int kk = 0; kk < 64; ++kk) {
                const float4 f = buf[kk & 3];
                if (kk < 60) buf[kk & 3] = __ldcg(Ab + (kk + 4) * 32);
                const uint32_t a0 = __float_as_uint(f.x), a1 = __float_as_uint(f.y);
                const uint32_t a2 = __float_as_uint(f.z), a3 = __float_as_uint(f.w);
#pragma unroll
                for (int nt = 0; nt < 4; nt++) {
                    const uint32_t bb0 = ld_u32h(bA[nt] + kk * 16);
                    const uint32_t bb1 = ld_u32h(bA[nt] + kk * 16 + 8);
                    mma_fp16(accA[nt], a0, a1, a2, a3, bb0, bb1);
                }
                if (isL) {
#pragma unroll
                    for (int nt = 0; nt < 4; nt++) {
                        const uint32_t bb0 = ld_u32h(bB[nt] + kk * 16);
                        const uint32_t bb1 = ld_u32h(bB[nt] + kk * 16 + 8);
                        mma_fp16(accB[nt], a0, a1, a2, a3, bb0, bb1);
                    }
                }
            }

            // gate writes (exclusive rows per warp)
            const int rw = mq * 16 + g;
            if (isL) {
                if (s < TT) {   // L1 output only needed for s<=255
#pragma unroll
                    for (int nt = 0; nt < 4; nt++) {
                        const int cc = nt * 8 + 2 * q;
                        *(float2*)(L1g + rw * FG_STR + cc)       = make_float2(accA[nt][0], accA[nt][1]);
                        *(float2*)(L1g + (rw + 8) * FG_STR + cc) = make_float2(accA[nt][2], accA[nt][3]);
                    }
                }
#pragma unroll
                for (int nt = 0; nt < 4; nt++) {
                    const int cc = nt * 8 + 2 * q;
                    *(float2*)(PIg + rw * FG_STR + cc)       = make_float2(accB[nt][0], accB[nt][1]);
                    *(float2*)(PIg + (rw + 8) * FG_STR + cc) = make_float2(accB[nt][2], accB[nt][3]);
                }
            } else {
#pragma unroll
                for (int nt = 0; nt < 4; nt++) {
                    const int cc = nt * 8 + 2 * q;
                    *(float2*)(PHg + rw * FG_STR + cc)       = make_float2(accA[nt][0], accA[nt][1]);
                    *(float2*)(PHg + (rw + 8) * FG_STR + cc) = make_float2(accA[nt][2], accA[nt][3]);
                }
            }
        }
        __syncthreads();

        // ---- layer 1 elementwise: h1(s), s<=255 ----
        if (s < TT) {
            float gi0 = xi0, gf0 = xf0, gg0 = xg0, go0 = xo0;
            float gi1 = xi1, gf1 = xf1, gg1 = xg2_, go1 = xo1;
            if (s >= 1) {
                gi0 += L1g[r0 * FG_STR + j];      gf0 += L1g[r0 * FG_STR + 8 + j];
                gg0 += L1g[r0 * FG_STR + 16 + j]; go0 += L1g[r0 * FG_STR + 24 + j];
                gi1 += L1g[r1 * FG_STR + j];      gf1 += L1g[r1 * FG_STR + 8 + j];
                gg1 += L1g[r1 * FG_STR + 16 + j]; go1 += L1g[r1 * FG_STR + 24 + j];
            }
            c1a = sigf(gf0) * c1a + sigf(gi0) * tanhf(gg0);
            c1b = sigf(gf1) * c1b + sigf(gi1) * tanhf(gg1);
            const float h0v = sigf(go0) * tanhf(c1a);
            const float h1v = sigf(go1) * tanhf(c1b);
            __half* d = h1F + (size_t)(s & 1) * 65536;
            d[off0] = __float2half_rn(h0v);
            d[off1] = __float2half_rn(h1v);
        }

        // ---- layer 2 elementwise: h2(s-1), s>=1 ----
        if (s >= 1) {
            float gi0 = PIg[r0 * FG_STR + j]      + bias2[0];
            float gf0 = PIg[r0 * FG_STR + 8 + j]  + bias2[1];
            float gg0 = PIg[r0 * FG_STR + 16 + j] + bias2[2];
            float go0 = PIg[r0 * FG_STR + 24 + j] + bias2[3];
            float gi1 = PIg[r1 * FG_STR + j]      + bias2[0];
            float gf1 = PIg[r1 * FG_STR + 8 + j]  + bias2[1];
            float gg1 = PIg[r1 * FG_STR + 16 + j] + bias2[2];
            float go1 = PIg[r1 * FG_STR + 24 + j] + bias2[3];
            if (s >= 2) {
                gi0 += PHg[r0 * FG_STR + j];      gf0 += PHg[r0 * FG_STR + 8 + j];
                gg0 += PHg[r0 * FG_STR + 16 + j]; go0 += PHg[r0 * FG_STR + 24 + j];
                gi1 += PHg[r1 * FG_STR + j];      gf1 += PHg[r1 * FG_STR + 8 + j];
                gg1 += PHg[r1 * FG_STR + 16 + j]; go1 += PHg[r1 * FG_STR + 24 + j];
            }
            c2a = sigf(gf0) * c2a + sigf(gi0) * tanhf(gg0);
            c2b = sigf(gf1) * c2b + sigf(gi1) * tanhf(gg1);
            const float h0v = sigf(go0) * tanhf(c2a);
            const float h1v = sigf(go1) * tanhf(c2b);
            if (s < TT) {           // h2(s-1) consumed at step s+1 (needs s-1 >= ... valid while s<=255)
                __half* d = h2F + (size_t)(s & 1) * 65536;
                d[off0] = __float2half_rn(h0v);
                d[off1] = __float2half_rn(h1v);
            }
            if (s == TT) {          // h2(255): final output for MLP
                hlast[r0 * HH + k_own] = __float2half_rn(h0v);
                hlast[r1 * HH + k_own] = __float2half_rn(h1v);
            }
        }

        if (s < TT) grid_bar();
    }
}

// ------------------------- final MLP layer 3 ---------------------------------
__global__ void mlp3_kernel(const __half* __restrict__ z2, const float* __restrict__ W3,
                            const float* __restrict__ b3, float* __restrict__ out)
{
    __shared__ float red[8];
    const int b = blockIdx.x;
    float s = 0.f;
    for (int k = threadIdx.x; k < 512; k += 256)
        s += __half2float(z2[b * 512 + k]) * W3[k];
#pragma unroll
    for (int o = 16; o; o >>= 1) s += __shfl_down_sync(0xffffffffu, s, o);
    if ((threadIdx.x & 31) == 0) red[threadIdx.x >> 5] = s;
    __syncthreads();
    if (threadIdx.x < 8) {
        s = red[threadIdx.x];
#pragma unroll
        for (int o = 4; o; o >>= 1) s += __shfl_down_sync(0xffu, s, o);
        if (threadIdx.x == 0) out[b] = s + b3[0];
    }
}

// ------------------------- launcher ------------------------------------------
extern "C" void kernel_launch(void* const* d_in, const int* in_sizes, int n_in,
                              void* d_out, int out_size)
{
    const float* xx       = (const float*)d_in[0];
    const float* l1_Wih0  = (const float*)d_in[1];
    const float* l1_bih0  = (const float*)d_in[2];
    const float* l1_bhh0  = (const float*)d_in[3];
    const float* l1_Wih1  = (const float*)d_in[4];
    const float* l1_bih1  = (const float*)d_in[5];
    const float* l1_bhh1  = (const float*)d_in[6];
    const float* l2_Wih0  = (const float*)d_in[7];
    const float* l2_Whh0  = (const float*)d_in[8];
    const float* l2_bih0  = (const float*)d_in[9];
    const float* l2_bhh0  = (const float*)d_in[10];
    const float* l2_Wih1  = (const float*)d_in[11];
    const float* l2_Whh1  = (const float*)d_in[12];
    const float* l2_bih1  = (const float*)d_in[13];
    const float* l2_bhh1  = (const float*)d_in[14];
    const float* mlp_W1   = (const float*)d_in[15];
    const float* mlp_b1   = (const float*)d_in[16];
    const float* mlp_W2   = (const float*)d_in[17];
    const float* mlp_b2   = (const float*)d_in[18];
    const float* mlp_W3   = (const float*)d_in[19];
    const float* mlp_b3   = (const float*)d_in[20];
    float* out = (float*)d_out;

    void* p;
    cudaGetSymbolAddress(&p, g_gates); float*  gates = (float*)p;
    cudaGetSymbolAddress(&p, g_w16);   __half* w16   = (__half*)p;
    cudaGetSymbolAddress(&p, g_h1);    __half* h1    = (__half*)p;
    cudaGetSymbolAddress(&p, g_h2);    __half* h2    = (__half*)p;
    cudaGetSymbolAddress(&p, g_h1F);   __half* h1F   = (__half*)p;
    cudaGetSymbolAddress(&p, g_h2F);   __half* h2F   = (__half*)p;
    cudaGetSymbolAddress(&p, g_hlast); __half* hlast = (__half*)p;
    cudaGetSymbolAddress(&p, g_z1);    __half* z1    = (__half*)p;
    cudaGetSymbolAddress(&p, g_z2);    __half* z2    = (__half*)p;

    const int lstm1_smem = 4 * L_ST * 2;     // 81920 B
    const int gemm_smem  = 4 * G_STG * 2;    // 122880 B
    const int fused_smem = F_SMEM_B;         // 228864 B
    cudaFuncSetAttribute((const void*)gemm16_kernel<0,0>, cudaFuncAttributeMaxDynamicSharedMemorySize, gemm_smem);
    cudaFuncSetAttribute((const void*)gemm16_kernel<1,1>, cudaFuncAttributeMaxDynamicSharedMemorySize, gemm_smem);
    cudaFuncSetAttribute((const void*)lstm1_16_kernel,    cudaFuncAttributeMaxDynamicSharedMemorySize, lstm1_smem);
    cudaFuncSetAttribute((const void*)fused_recur_kernel, cudaFuncAttributeMaxDynamicSharedMemorySize, fused_smem);

    const dim3 blk(256);

    // [0] fp32 -> fp16 (xx + 6 weight matrices)
    convert_kernel<<<4849664 / 256, blk>>>(xx, l1_Wih0, l1_Wih1, l2_Wih0, l2_Wih1, mlp_W1, mlp_W2);

    // [1][2] lstm1 (fused, f gate skipped)
    lstm1_16_kernel<<<dim3(HH / 128, BT / 128), blk, lstm1_smem>>>(w16 + X16_OFF, 256, w16 + W_L1A,
                                                                   l1_bih0, l1_bhh0, h1, BT, 256);
    lstm1_16_kernel<<<dim3(HH / 128, BT / 128), blk, lstm1_smem>>>(h1, HH, w16 + W_L1B,
                                                                   l1_bih1, l1_bhh1, h2, BT, HH);

    // [3][4] lstm2 layer-0 xg GEMM (split halves) ; [5] fused dual recurrence
    gemm16_kernel<0,0><<<dim3(G4 / 256, 64), blk, gemm_smem>>>(h2, HH, w16 + W_L2A, l2_bih0, l2_bhh0,
                                                               gates, BT / 2, G4, HH);
    gemm16_kernel<0,0><<<dim3(G4 / 256, 64), blk, gemm_smem>>>(h2 + (size_t)(BT / 2) * HH, HH, w16 + W_L2A,
                                                               l2_bih0, l2_bhh0,
                                                               gates + (size_t)(BT / 2) * G4, BT / 2, G4, HH);
    fused_recur_kernel<<<128, blk, fused_smem>>>(gates, l2_Whh0, l2_Wih1, l2_Whh1,
                                                 l2_bih1, l2_bhh1, hlast, h1F, h2F);

    // [6][7][8] MLP on h2(255)
    gemm16_kernel<1,1><<<dim3(HH / 256, 1), blk, gemm_smem>>>(hlast, HH, w16 + W_M1, mlp_b1, nullptr,
                                                              z1, BB, HH, HH);
    gemm16_kernel<1,1><<<dim3((HH / 2) / 256, 1), blk, gemm_smem>>>(z1, HH, w16 + W_M2, mlp_b2, nullptr,
                                                                    z2, BB, HH / 2, HH);
    mlp3_kernel<<<BB, blk>>>(z2, mlp_W3, mlp_b3, out);
}

// round 10
// speedup vs baseline: 1.1671x; 1.0727x over previous
#include <cuda_runtime.h>
#include <cuda_fp16.h>
#include <cstdint>
#include <cstddef>

#define HH 1024
#define TT 256
#define BB 64
#define BT (BB*TT)       /* 16384 */
#define G4 (4*HH)        /* 4096 */

/* fp16 GEMM tile constants (stride in halves) */
#define HSTR 40
#define L_ST (256*HSTR)             /* lstm1 stage halves (A128+B128) */
#define G_AT (128*HSTR)             /* gemm A region halves */
#define G_STG (384*HSTR)            /* gemm stage halves (A128+B256)  */

/* fused recurrence smem (bytes) */
#define FW_STR 1032                 /* slab row stride (halves)      */
#define F_G_B  (3*32*FW_STR*2)      /* 198144: gate region base      */
#define FG_STR 40                   /* gate buffer row stride (f32)  */
#define FG_SZ  (64*FG_STR*4)        /* 10240 B per gate buffer       */
#define F_SMEM_B (F_G_B + 3*FG_SZ)  /* 228864 B                      */

/* fp16 scratch offsets (halves) */
#define X16_OFF  0u
#define W_L1A    4194304u
#define W_L1B    5242880u
#define W_L2A    9437184u
#define W_L2B    13631488u
#define W_M1     17825792u
#define W_M2     18874368u
#define W16_TOT  19398656u

// ------------------------- scratch (device globals) --------------------------
__device__ __align__(256) float  g_gates[(size_t)BT * G4];   // fp32 xg1 scratch
__device__ __align__(256) __half g_w16[W16_TOT];             // converted x + weights
__device__ __align__(256) __half g_h1[(size_t)BT * HH];
__device__ __align__(256) __half g_h2[(size_t)BT * HH];
__device__ __align__(256) __half g_h1F[2 * 65536];           // h1 fragment buffer [parity]
__device__ __align__(256) __half g_h2F[2 * 65536];           // h2 fragment buffer [parity]
__device__ __align__(256) __half g_hlast[BB * HH];           // final h2(255) for MLP
__device__ __align__(256) __half g_z1[BB * HH];
__device__ __align__(256) __half g_z2[BB * (HH/2)];
__device__ volatile unsigned g_cnt = 0;
__device__ volatile unsigned g_sense = 0;

// ------------------------- helpers ------------------------------------------
__device__ __forceinline__ uint32_t ld_u32h(const __half* p) {
    return *(const uint32_t*)p;
}
__device__ __forceinline__ void mma_fp16(float c[4],
                                         uint32_t a0, uint32_t a1, uint32_t a2, uint32_t a3,
                                         uint32_t b0, uint32_t b1) {
    asm volatile(
        "mma.sync.aligned.m16n8k16.row.col.f32.f16.f16.f32 "
        "{%0,%1,%2,%3}, {%4,%5,%6,%7}, {%8,%9}, {%0,%1,%2,%3};"
        : "+f"(c[0]), "+f"(c[1]), "+f"(c[2]), "+f"(c[3])
        : "r"(a0), "r"(a1), "r"(a2), "r"(a3), "r"(b0), "r"(b1));
}
__device__ __forceinline__ float sigf(float x) { return 1.0f / (1.0f + expf(-x)); }

__device__ __forceinline__ void cp16(uint32_t dsh, const void* src) {
    asm volatile("cp.async.cg.shared.global [%0], [%1], 16;" :: "r"(dsh), "l"(src));
}
__device__ __forceinline__ void cp_commit() { asm volatile("cp.async.commit_group;"); }

// =============================================================================
// fp32 -> fp16 conversion of xx + 6 weight matrices (one launch)
// =============================================================================
__global__ void convert_kernel(const float* __restrict__ xx,
                               const float* __restrict__ w0, const float* __restrict__ w1,
                               const float* __restrict__ w2, const float* __restrict__ w3,
                               const float* __restrict__ w4, const float* __restrict__ w5)
{
    const uint32_t i4 = blockIdx.x * blockDim.x + threadIdx.x;   // float4 index
    const float* src; uint32_t base4;
    if      (i4 < 1048576u) { src = xx; base4 = 0u; }
    else if (i4 < 1310720u) { src = w0; base4 = 1048576u; }
    else if (i4 < 2359296u) { src = w1; base4 = 1310720u; }
    else if (i4 < 3407872u) { src = w2; base4 = 2359296u; }
    else if (i4 < 4456448u) { src = w3; base4 = 3407872u; }
    else if (i4 < 4718592u) { src = w4; base4 = 4456448u; }
    else                    { src = w5; base4 = 4718592u; }
    const float4 v = ((const float4*)src)[i4 - base4];
    __half2* dst = (__half2*)(g_w16 + (size_t)i4 * 4);
    dst[0] = __floats2half2_rn(v.x, v.y);
    dst[1] = __floats2half2_rn(v.z, v.w);
}

// =============================================================================
// fp16 GEMM: C = A @ W^T (+bias, +ReLU). BM=128, BN=256, BK=32, 4-stage.
// =============================================================================
template<int RELU, int HOUT>
__launch_bounds__(256, 1)
__global__ void gemm16_kernel(const __half* __restrict__ A, long long asr,
                              const __half* __restrict__ W,
                              const float* __restrict__ b1p, const float* __restrict__ b2p,
                              void* __restrict__ Cv, int M, int N, int K)
{
    extern __shared__ __half smh[];
    const int tid = threadIdx.x, lane = tid & 31, warp = tid >> 5;
    const int wm = warp >> 2, wn = warp & 3;
    const int g = lane >> 2, q = lane & 3;
    const int mb = blockIdx.y * 128, nb = blockIdx.x * 256;

    float acc[4][8][4];
#pragma unroll
    for (int a = 0; a < 4; a++)
#pragma unroll
        for (int b = 0; b < 8; b++)
#pragma unroll
            for (int c = 0; c < 4; c++) acc[a][b][c] = 0.0f;

    const uint32_t smb = (uint32_t)__cvta_generic_to_shared(smh);
    const __half* aptr[2]; uint32_t adst[2];
#pragma unroll
    for (int i = 0; i < 2; i++) {
        const int slot = tid + i * 256;
        const int row = slot >> 2, kc = (slot & 3) * 8;
        int gr = mb + row; if (gr > M - 1) gr = M - 1;
        aptr[i] = A + (size_t)gr * asr + kc;
        adst[i] = smb + (uint32_t)((row * HSTR + kc) * 2);
    }
    const __half* bptr[4]; uint32_t bdst[4];
#pragma unroll
    for (int i = 0; i < 4; i++) {
        const int slot = tid + i * 256;
        const int row = slot >> 2, kc = (slot & 3) * 8;
        bptr[i] = W + (size_t)(nb + row) * K + kc;
        bdst[i] = smb + (uint32_t)((G_AT + row * HSTR + kc) * 2);
    }

    const int KT = K >> 5;
    auto issue = [&](int kt) {
        const uint32_t so = (uint32_t)((kt & 3) * G_STG * 2);
        const int koff = kt * 32;
#pragma unroll
        for (int i = 0; i < 2; i++) cp16(adst[i] + so, aptr[i] + koff);
#pragma unroll
        for (int i = 0; i < 4; i++) cp16(bdst[i] + so, bptr[i] + koff);
        cp_commit();
    };

    const int pre = KT < 3 ? KT : 3;
    for (int s = 0; s < pre; ++s) issue(s);

    for (int kt = 0; kt < KT; ++kt) {
        if (kt < KT - 2)       asm volatile("cp.async.wait_group 2;");
        else if (kt == KT - 2) asm volatile("cp.async.wait_group 1;");
        else                   asm volatile("cp.async.wait_group 0;");
        __syncthreads();
        if (kt + 3 < KT) issue(kt + 3);

        const __half* Ab = smh + (kt & 3) * G_STG;
        const __half* Bb = Ab + G_AT;
#pragma unroll
        for (int kk = 0; kk < 32; kk += 16) {
            uint32_t af[4][4], bfr[8][2];
#pragma unroll
            for (int mt = 0; mt < 4; mt++) {
                const int r = wm * 64 + mt * 16 + g;
                af[mt][0] = ld_u32h(Ab + r * HSTR + kk + 2 * q);
                af[mt][1] = ld_u32h(Ab + (r + 8) * HSTR + kk + 2 * q);
                af[mt][2] = ld_u32h(Ab + r * HSTR + kk + 2 * q + 8);
                af[mt][3] = ld_u32h(Ab + (r + 8) * HSTR + kk + 2 * q + 8);
            }
#pragma unroll
            for (int nt = 0; nt < 8; nt++) {
                const int n = wn * 64 + nt * 8 + g;
                bfr[nt][0] = ld_u32h(Bb + n * HSTR + kk + 2 * q);
                bfr[nt][1] = ld_u32h(Bb + n * HSTR + kk + 2 * q + 8);
            }
#pragma unroll
            for (int mt = 0; mt < 4; mt++)
#pragma unroll
                for (int nt = 0; nt < 8; nt++)
                    mma_fp16(acc[mt][nt], af[mt][0], af[mt][1], af[mt][2], af[mt][3],
                             bfr[nt][0], bfr[nt][1]);
        }
    }

#pragma unroll
    for (int mt = 0; mt < 4; mt++) {
#pragma unroll
        for (int nt = 0; nt < 8; nt++) {
            const int row0 = mb + wm * 64 + mt * 16 + g;
            const int col  = nb + wn * 64 + nt * 8 + 2 * q;
            const float b0v = (b1p ? b1p[col]     : 0.f) + (b2p ? b2p[col]     : 0.f);
            const float b1v = (b1p ? b1p[col + 1] : 0.f) + (b2p ? b2p[col + 1] : 0.f);
            float v0 = acc[mt][nt][0] + b0v, v1 = acc[mt][nt][1] + b1v;
            float v2 = acc[mt][nt][2] + b0v, v3 = acc[mt][nt][3] + b1v;
            if (RELU) {
                v0 = fmaxf(v0, 0.f); v1 = fmaxf(v1, 0.f);
                v2 = fmaxf(v2, 0.f); v3 = fmaxf(v3, 0.f);
            }
            if (HOUT) {
                __half* C = (__half*)Cv;
                if (row0 < M)     *(__half2*)(C + (size_t)row0 * N + col)       = __floats2half2_rn(v0, v1);
                if (row0 + 8 < M) *(__half2*)(C + (size_t)(row0 + 8) * N + col) = __floats2half2_rn(v2, v3);
            } else {
                float* C = (float*)Cv;
                if (row0 < M)     *(float2*)(C + (size_t)row0 * N + col)       = make_float2(v0, v1);
                if (row0 + 8 < M) *(float2*)(C + (size_t)(row0 + 8) * N + col) = make_float2(v2, v3);
            }
        }
    }
}

// =============================================================================
// fused lstm1 (fp16): h = sig(o)*tanh(sig(i)*tanh(g)); f gate skipped.
// =============================================================================
__launch_bounds__(256, 1)
__global__ void lstm1_16_kernel(const __half* __restrict__ A, long long asr,
                                const __half* __restrict__ W,
                                const float* __restrict__ bih, const float* __restrict__ bhh,
                                __half* __restrict__ Hout, int M, int K)
{
    extern __shared__ __half smh[];
    const int tid = threadIdx.x, lane = tid & 31, warp = tid >> 5;
    const int wm = warp >> 2, wn = warp & 3;
    const int g = lane >> 2, q = lane & 3;
    const int mb = blockIdx.y * 128, nb = blockIdx.x * 128;

    const uint32_t smb = (uint32_t)__cvta_generic_to_shared(smh);

    const __half* aptr[2]; uint32_t adst[2];
#pragma unroll
    for (int i = 0; i < 2; i++) {
        const int slot = tid + i * 256;
        const int row = slot >> 2, kc = (slot & 3) * 8;
        int gr = mb + row; if (gr > M - 1) gr = M - 1;
        aptr[i] = A + (size_t)gr * asr + kc;
        adst[i] = smb + (uint32_t)((row * HSTR + kc) * 2);
    }
    uint32_t bdst[2]; int brow[2], bkc[2];
#pragma unroll
    for (int i = 0; i < 2; i++) {
        const int slot = tid + i * 256;
        brow[i] = slot >> 2; bkc[i] = (slot & 3) * 8;
        bdst[i] = smb + (uint32_t)(((128 + brow[i]) * HSTR + bkc[i]) * 2);
    }

    const int KT = K >> 5;
    float keep[4][4][4];
    const int gset[3] = {0, 2, 3};

#pragma unroll 1
    for (int ph = 0; ph < 3; ++ph) {
        const int gate = gset[ph];
        const __half* Wb = W + ((size_t)(gate * HH + nb)) * K;

        float acc[4][4][4];
#pragma unroll
        for (int a = 0; a < 4; a++)
#pragma unroll
            for (int b = 0; b < 4; b++)
#pragma unroll
                for (int c = 0; c < 4; c++) acc[a][b][c] = 0.0f;

        auto issue = [&](int kt) {
            const int koff = kt * 32;
            const uint32_t so = (uint32_t)((kt & 3) * L_ST * 2);
#pragma unroll
            for (int i = 0; i < 2; i++) cp16(adst[i] + so, aptr[i] + koff);
#pragma unroll
            for (int i = 0; i < 2; i++) cp16(bdst[i] + so, Wb + (size_t)brow[i] * K + bkc[i] + koff);
            cp_commit();
        };

        const int pre = KT < 3 ? KT : 3;
        for (int s = 0; s < pre; ++s) issue(s);

        for (int kt = 0; kt < KT; ++kt) {
            if (kt < KT - 2)       asm volatile("cp.async.wait_group 2;");
            else if (kt == KT - 2) asm volatile("cp.async.wait_group 1;");
            else                   asm volatile("cp.async.wait_group 0;");
            __syncthreads();
            if (kt + 3 < KT) issue(kt + 3);

            const __half* Ab = smh + (kt & 3) * L_ST;
            const __half* Bb = Ab + 128 * HSTR;
#pragma unroll
            for (int kk = 0; kk < 32; kk += 16) {
                uint32_t af[4][4], bfr[4][2];
#pragma unroll
                for (int mt = 0; mt < 4; mt++) {
                    const int r = wm * 64 + mt * 16 + g;
                    af[mt][0] = ld_u32h(Ab + r * HSTR + kk + 2 * q);
                    af[mt][1] = ld_u32h(Ab + (r + 8) * HSTR + kk + 2 * q);
                    af[mt][2] = ld_u32h(Ab + r * HSTR + kk + 2 * q + 8);
                    af[mt][3] = ld_u32h(Ab + (r + 8) * HSTR + kk + 2 * q + 8);
                }
#pragma unroll
                for (int nt = 0; nt < 4; nt++) {
                    const int n = wn * 32 + nt * 8 + g;
                    bfr[nt][0] = ld_u32h(Bb + n * HSTR + kk + 2 * q);
                    bfr[nt][1] = ld_u32h(Bb + n * HSTR + kk + 2 * q + 8);
                }
#pragma unroll
                for (int mt = 0; mt < 4; mt++)
#pragma unroll
                    for (int nt = 0; nt < 4; nt++)
                        mma_fp16(acc[mt][nt], af[mt][0], af[mt][1], af[mt][2], af[mt][3],
                                 bfr[nt][0], bfr[nt][1]);
            }
        }
        __syncthreads();

#pragma unroll
        for (int mt = 0; mt < 4; mt++) {
#pragma unroll
            for (int nt = 0; nt < 4; nt++) {
                const int gcol = gate * HH + nb + wn * 32 + nt * 8 + 2 * q;
                const float b0 = bih[gcol] + bhh[gcol];
                const float b1 = bih[gcol + 1] + bhh[gcol + 1];
                if (ph == 0) {
                    keep[mt][nt][0] = sigf(acc[mt][nt][0] + b0);
                    keep[mt][nt][1] = sigf(acc[mt][nt][1] + b1);
                    keep[mt][nt][2] = sigf(acc[mt][nt][2] + b0);
                    keep[mt][nt][3] = sigf(acc[mt][nt][3] + b1);
                } else if (ph == 1) {
                    keep[mt][nt][0] *= tanhf(acc[mt][nt][0] + b0);
                    keep[mt][nt][1] *= tanhf(acc[mt][nt][1] + b1);
                    keep[mt][nt][2] *= tanhf(acc[mt][nt][2] + b0);
                    keep[mt][nt][3] *= tanhf(acc[mt][nt][3] + b1);
                } else {
                    const int row0 = mb + wm * 64 + mt * 16 + g;
                    const int colh = nb + wn * 32 + nt * 8 + 2 * q;
                    const float v0 = sigf(acc[mt][nt][0] + b0) * tanhf(keep[mt][nt][0]);
                    const float v1 = sigf(acc[mt][nt][1] + b1) * tanhf(keep[mt][nt][1]);
                    const float v2 = sigf(acc[mt][nt][2] + b0) * tanhf(keep[mt][nt][2]);
                    const float v3 = sigf(acc[mt][nt][3] + b1) * tanhf(keep[mt][nt][3]);
                    if (row0 < M)     *(__half2*)(Hout + (size_t)row0 * HH + colh)       = __floats2half2_rn(v0, v1);
                    if (row0 + 8 < M) *(__half2*)(Hout + (size_t)(row0 + 8) * HH + colh) = __floats2half2_rn(v2, v3);
                }
            }
        }
    }
}

// ------------------------- 128-CTA grid barrier -------------------------------
__device__ __forceinline__ void grid_bar()
{
    __threadfence();
    __syncthreads();
    if (threadIdx.x == 0) {
        const unsigned gen = g_sense;
        const unsigned arrived = atomicAdd((unsigned*)&g_cnt, 1u);
        if (arrived == 127u) {
            g_cnt = 0;
            __threadfence();
            atomicAdd((unsigned*)&g_sense, 1u);
        } else {
            while (g_sense == gen) { __nanosleep(16); }
        }
        __threadfence();
    }
    __syncthreads();
}

// =============================================================================
// FUSED DUAL-LAYER RECURRENCE (lstm2 layer0 + layer1, software-pipelined)
//
// 128 CTAs x 256 thr; CTA owns 8 h cols for BOTH layers (32 gate cols each).
// SMEM: 3 fp16 weight slabs (Whh1, Wih2, Whh2) + 3 fp32 gate buffers.
// Pipeline step s (0..256): layer1 computes h1(s) from xg1(s) + h1(s-1)@Whh1;
// layer2 computes h2(s-1) from h1(s-1)@Wih2 + b2 + h2(s-2)@Whh2.
// Warps 0-3: L1 + I2 (shared h1 A-fragments); warps 4-7: H2.
// A-fragments stream from global via __ldcg with an 8-deep rolling ring
// (L2 latency / 8 = ~75 cyc/iter floor). One 128-CTA barrier per step.
// =============================================================================
__launch_bounds__(256, 1)
__global__ void fused_recur_kernel(const float* __restrict__ xg1,   // [BT,4096] f32
                                   const float* __restrict__ Whh1,  // [4096,1024] f32
                                   const float* __restrict__ Wih2,  // [4096,1024] f32
                                   const float* __restrict__ Whh2,  // [4096,1024] f32
                                   const float* __restrict__ b2i,
                                   const float* __restrict__ b2h,
                                   __half* __restrict__ hlast,      // [64,1024]
                                   __half* __restrict__ h1F,        // [2][65536]
                                   __half* __restrict__ h2F)        // [2][65536]
{
    extern __shared__ char smc[];
    __half* slab = (__half*)smc;                       // 3 x [32][1032]
    float*  L1g  = (float*)(smc + F_G_B);              // [64][40]
    float*  PIg  = (float*)(smc + F_G_B + FG_SZ);      // [64][40]
    float*  PHg  = (float*)(smc + F_G_B + 2 * FG_SZ);  // [64][40]

    const int tid = threadIdx.x, lane = tid & 31, warp = tid >> 5;
    const int g = lane >> 2, q = lane & 3;
    const int n0 = blockIdx.x * 8;

    // ---- load 3 weight slabs (fp16, conflict-free stride 1032) ----
#pragma unroll 1
    for (int c = 0; c < 96; c++) {
        const float* Wsrc = (c < 32) ? Whh1 : (c < 64) ? Wih2 : Whh2;
        const int rr = c & 31;
        const int row = (rr >> 3) * HH + n0 + (rr & 7);
        const float4 v = *(const float4*)(Wsrc + (size_t)row * HH + tid * 4);
        __half* d = slab + c * FW_STR + tid * 4;
        d[0] = __float2half_rn(v.x); d[1] = __float2half_rn(v.y);
        d[2] = __float2half_rn(v.z); d[3] = __float2half_rn(v.w);
    }
    __syncthreads();

    const __half* Ws1 = slab;
    const __half* Wi2 = slab + 32 * FW_STR;
    const __half* Ws2 = slab + 64 * FW_STR;

    // ---- mma role: warps 0-3 (L1+I2 on h1), warps 4-7 (H2 on h2) ----
    const int mq = warp & 3;            // M quarter (rows mq*16..mq*16+15)
    const int isL = (warp < 4);
    const __half* bA[4]; const __half* bB[4];
#pragma unroll
    for (int nt = 0; nt < 4; nt++) {
        const int n = nt * 8 + g;
        bA[nt] = (isL ? Ws1 : Ws2) + n * FW_STR + 2 * q;
        bB[nt] = Wi2 + n * FW_STR + 2 * q;   // only used by warps 0-3
    }

    // ---- elementwise mapping: thread -> (r0, r1, col j) ----
    const int j = tid & 7, r0 = tid >> 3, r1 = r0 + 32;
    const int k_own = n0 + j;
    const int kkw = k_own >> 4, kc = k_own & 15;
    auto frag_off = [&](int r) {
        const int mqw = r >> 4, rr = r & 15;
        const int lw = (rr & 7) * 4 + ((kc & 7) >> 1);
        const int s2 = ((rr >= 8) ? 1 : 0) + ((kc >= 8) ? 2 : 0);
        return ((mqw * 64 + kkw) * 32 + lw) * 8 + s2 * 2 + (kc & 1);
    };
    const int off0 = frag_off(r0), off1 = frag_off(r1);

    // layer-2 per-column biases
    float bias2[4];
#pragma unroll
    for (int gg = 0; gg < 4; gg++)
        bias2[gg] = b2i[gg * HH + k_own] + b2h[gg * HH + k_own];

    float c1a = 0.f, c1b = 0.f, c2a = 0.f, c2b = 0.f;

#pragma unroll 1
    for (int s = 0; s <= TT; s++) {
        // xg1 prefetch for layer1 (valid s<=255)
        float xi0 = 0.f, xf0 = 0.f, xg0 = 0.f, xo0 = 0.f;
        float xi1 = 0.f, xf1 = 0.f, xg2_ = 0.f, xo1 = 0.f;
        if (s < TT) {
            const size_t x0 = ((size_t)(r0 * TT + s)) * G4 + k_own;
            const size_t x1 = ((size_t)(r1 * TT + s)) * G4 + k_own;
            xi0 = xg1[x0]; xf0 = xg1[x0 + 1024]; xg0 = xg1[x0 + 2048]; xo0 = xg1[x0 + 3072];
            xi1 = xg1[x1]; xf1 = xg1[x1 + 1024]; xg2_ = xg1[x1 + 2048]; xo1 = xg1[x1 + 3072];
        }

        // ---- mma phase ----
        const int par = (s - 1) & 1;
        const int doA = isL ? (s >= 1) : (s >= 2);
        if (doA) {
            const float4* Ab = (const float4*)((isL ? h1F : h2F) + (size_t)par * 65536)
                               + (size_t)mq * 64 * 32 + lane;

            float accA[4][4], accB[4][4];
#pragma unroll
            for (int nt = 0; nt < 4; nt++)
#pragma unroll
                for (int cc = 0; cc < 4; cc++) { accA[nt][cc] = 0.f; accB[nt][cc] = 0.f; }

            // 8-deep rolling ring of A fragments
            float4 buf[8];
#pragma unroll
            for (int p = 0; p < 8; p++) buf[p] = __ldcg(Ab + p * 32);

#pragma unroll 8
            for (int kk = 0; kk < 64; ++kk) {
                const float4 f = buf[kk & 7];
                if (kk < 56) buf[kk & 7] = __ldcg(Ab + (kk + 8) * 32);
                const uint32_t a0 = __float_as_uint(f.x), a1 = __float_as_uint(f.y);
                const uint32_t a2 = __float_as_uint(f.z), a3 = __float_as_uint(f.w);
#pragma unroll
                for (int nt = 0; nt < 4; nt++) {
                    const uint32_t bb0 = ld_u32h(bA[nt] + kk * 16);
                    const uint32_t bb1 = ld_u32h(bA[nt] + kk * 16 + 8);
                    mma_fp16(accA[nt], a0, a1, a2, a3, bb0, bb1);
                }
                if (isL) {
#pragma unroll
                    for (int nt = 0; nt < 4; nt++) {
                        const uint32_t bb0 = ld_u32h(bB[nt] + kk * 16);
                        const uint32_t bb1 = ld_u32h(bB[nt] + kk * 16 + 8);
                        mma_fp16(accB[nt], a0, a1, a2, a3, bb0, bb1);
                    }
                }
            }

            // gate writes (exclusive rows per warp)
            const int rw = mq * 16 + g;
            if (isL) {
                if (s < TT) {
#pragma unroll
                    for (int nt = 0; nt < 4; nt++) {
                        const int cc = nt * 8 + 2 * q;
                        *(float2*)(L1g + rw * FG_STR + cc)       = make_float2(accA[nt][0], accA[nt][1]);
                        *(float2*)(L1g + (rw + 8) * FG_STR + cc) = make_float2(accA[nt][2], accA[nt][3]);
                    }
                }
#pragma unroll
                for (int nt = 0; nt < 4; nt++) {
                    const int cc = nt * 8 + 2 * q;
                    *(float2*)(PIg + rw * FG_STR + cc)       = make_float2(accB[nt][0], accB[nt][1]);
                    *(float2*)(PIg + (rw + 8) * FG_STR + cc) = make_float2(accB[nt][2], accB[nt][3]);
                }
            } else {
#pragma unroll
                for (int nt = 0; nt < 4; nt++) {
                    const int cc = nt * 8 + 2 * q;
                    *(float2*)(PHg + rw * FG_STR + cc)       = make_float2(accA[nt][0], accA[nt][1]);
                    *(float2*)(PHg + (rw + 8) * FG_STR + cc) = make_float2(accA[nt][2], accA[nt][3]);
                }
            }
        }
        __syncthreads();

        // ---- layer 1 elementwise: h1(s), s<=255 ----
        if (s < TT) {
            float gi0 = xi0, gf0 = xf0, gg0 = xg0, go0 = xo0;
            float gi1 = xi1, gf1 = xf1, gg1 = xg2_, go1 = xo1;
            if (s >= 1) {
                gi0 += L1g[r0 * FG_STR + j];      gf0 += L1g[r0 * FG_STR + 8 + j];
                gg0 += L1g[r0 * FG_STR + 16 + j]; go0 += L1g[r0 * FG_STR + 24 + j];
                gi1 += L1g[r1 * FG_STR + j];      gf1 += L1g[r1 * FG_STR + 8 + j];
                gg1 += L1g[r1 * FG_STR + 16 + j]; go1 += L1g[r1 * FG_STR + 24 + j];
            }
            c1a = sigf(gf0) * c1a + sigf(gi0) * tanhf(gg0);
            c1b = sigf(gf1) * c1b + sigf(gi1) * tanhf(gg1);
            const float h0v = sigf(go0) * tanhf(c1a);
            const float h1v = sigf(go1) * tanhf(c1b);
            __half* d = h1F + (size_t)(s & 1) * 65536;
            d[off0] = __float2half_rn(h0v);
            d[off1] = __float2half_rn(h1v);
        }

        // ---- layer 2 elementwise: h2(s-1), s>=1 ----
        if (s >= 1) {
            float gi0 = PIg[r0 * FG_STR + j]      + bias2[0];
            float gf0 = PIg[r0 * FG_STR + 8 + j]  + bias2[1];
            float gg0 = PIg[r0 * FG_STR + 16 + j] + bias2[2];
            float go0 = PIg[r0 * FG_STR + 24 + j] + bias2[3];
            float gi1 = PIg[r1 * FG_STR + j]      + bias2[0];
            float gf1 = PIg[r1 * FG_STR + 8 + j]  + bias2[1];
            float gg1 = PIg[r1 * FG_STR + 16 + j] + bias2[2];
            float go1 = PIg[r1 * FG_STR + 24 + j] + bias2[3];
            if (s >= 2) {
                gi0 += PHg[r0 * FG_STR + j];      gf0 += PHg[r0 * FG_STR + 8 + j];
                gg0 += PHg[r0 * FG_STR + 16 + j]; go0 += PHg[r0 * FG_STR + 24 + j];
                gi1 += PHg[r1 * FG_STR + j];      gf1 += PHg[r1 * FG_STR + 8 + j];
                gg1 += PHg[r1 * FG_STR + 16 + j]; go1 += PHg[r1 * FG_STR + 24 + j];
            }
            c2a = sigf(gf0) * c2a + sigf(gi0) * tanhf(gg0);
            c2b = sigf(gf1) * c2b + sigf(gi1) * tanhf(gg1);
            const float h0v = sigf(go0) * tanhf(c2a);
            const float h1v = sigf(go1) * tanhf(c2b);
            if (s < TT) {
                __half* d = h2F + (size_t)(s & 1) * 65536;
                d[off0] = __float2half_rn(h0v);
                d[off1] = __float2half_rn(h1v);
            }
            if (s == TT) {
                hlast[r0 * HH + k_own] = __float2half_rn(h0v);
                hlast[r1 * HH + k_own] = __float2half_rn(h1v);
            }
        }

        if (s < TT) grid_bar();
    }
}

// ------------------------- final MLP layer 3 ---------------------------------
__global__ void mlp3_kernel(const __half* __restrict__ z2, const float* __restrict__ W3,
                            const float* __restrict__ b3, float* __restrict__ out)
{
    __shared__ float red[8];
    const int b = blockIdx.x;
    float s = 0.f;
    for (int k = threadIdx.x; k < 512; k += 256)
        s += __half2float(z2[b * 512 + k]) * W3[k];
#pragma unroll
    for (int o = 16; o; o >>= 1) s += __shfl_down_sync(0xffffffffu, s, o);
    if ((threadIdx.x & 31) == 0) red[threadIdx.x >> 5] = s;
    __syncthreads();
    if (threadIdx.x < 8) {
        s = red[threadIdx.x];
#pragma unroll
        for (int o = 4; o; o >>= 1) s += __shfl_down_sync(0xffu, s, o);
        if (threadIdx.x == 0) out[b] = s + b3[0];
    }
}

// ------------------------- launcher ------------------------------------------
extern "C" void kernel_launch(void* const* d_in, const int* in_sizes, int n_in,
                              void* d_out, int out_size)
{
    const float* xx       = (const float*)d_in[0];
    const float* l1_Wih0  = (const float*)d_in[1];
    const float* l1_bih0  = (const float*)d_in[2];
    const float* l1_bhh0  = (const float*)d_in[3];
    const float* l1_Wih1  = (const float*)d_in[4];
    const float* l1_bih1  = (const float*)d_in[5];
    const float* l1_bhh1  = (const float*)d_in[6];
    const float* l2_Wih0  = (const float*)d_in[7];
    const float* l2_Whh0  = (const float*)d_in[8];
    const float* l2_bih0  = (const float*)d_in[9];
    const float* l2_bhh0  = (const float*)d_in[10];
    const float* l2_Wih1  = (const float*)d_in[11];
    const float* l2_Whh1  = (const float*)d_in[12];
    const float* l2_bih1  = (const float*)d_in[13];
    const float* l2_bhh1  = (const float*)d_in[14];
    const float* mlp_W1   = (const float*)d_in[15];
    const float* mlp_b1   = (const float*)d_in[16];
    const float* mlp_W2   = (const float*)d_in[17];
    const float* mlp_b2   = (const float*)d_in[18];
    const float* mlp_W3   = (const float*)d_in[19];
    const float* mlp_b3   = (const float*)d_in[20];
    float* out = (float*)d_out;

    void* p;
    cudaGetSymbolAddress(&p, g_gates); float*  gates = (float*)p;
    cudaGetSymbolAddress(&p, g_w16);   __half* w16   = (__half*)p;
    cudaGetSymbolAddress(&p, g_h1);    __half* h1    = (__half*)p;
    cudaGetSymbolAddress(&p, g_h2);    __half* h2    = (__half*)p;
    cudaGetSymbolAddress(&p, g_h1F);   __half* h1F   = (__half*)p;
    cudaGetSymbolAddress(&p, g_h2F);   __half* h2F   = (__half*)p;
    cudaGetSymbolAddress(&p, g_hlast); __half* hlast = (__half*)p;
    cudaGetSymbolAddress(&p, g_z1);    __half* z1    = (__half*)p;
    cudaGetSymbolAddress(&p, g_z2);    __half* z2    = (__half*)p;

    const int lstm1_smem = 4 * L_ST * 2;     // 81920 B
    const int gemm_smem  = 4 * G_STG * 2;    // 122880 B
    const int fused_smem = F_SMEM_B;         // 228864 B
    cudaFuncSetAttribute((const void*)gemm16_kernel<0,0>, cudaFuncAttributeMaxDynamicSharedMemorySize, gemm_smem);
    cudaFuncSetAttribute((const void*)gemm16_kernel<1,1>, cudaFuncAttributeMaxDynamicSharedMemorySize, gemm_smem);
    cudaFuncSetAttribute((const void*)lstm1_16_kernel,    cudaFuncAttributeMaxDynamicSharedMemorySize, lstm1_smem);
    cudaFuncSetAttribute((const void*)fused_recur_kernel, cudaFuncAttributeMaxDynamicSharedMemorySize, fused_smem);

    const dim3 blk(256);

    // [0] fp32 -> fp16 (xx + 6 weight matrices)
    convert_kernel<<<4849664 / 256, blk>>>(xx, l1_Wih0, l1_Wih1, l2_Wih0, l2_Wih1, mlp_W1, mlp_W2);

    // [1][2] lstm1 (fused, f gate skipped)
    lstm1_16_kernel<<<dim3(HH / 128, BT / 128), blk, lstm1_smem>>>(w16 + X16_OFF, 256, w16 + W_L1A,
                                                                   l1_bih0, l1_bhh0, h1, BT, 256);
    lstm1_16_kernel<<<dim3(HH / 128, BT / 128), blk, lstm1_smem>>>(h1, HH, w16 + W_L1B,
                                                                   l1_bih1, l1_bhh1, h2, BT, HH);

    // [3][4] lstm2 layer-0 xg GEMM (split halves) ; [5] fused dual recurrence
    gemm16_kernel<0,0><<<dim3(G4 / 256, 64), blk, gemm_smem>>>(h2, HH, w16 + W_L2A, l2_bih0, l2_bhh0,
                                                               gates, BT / 2, G4, HH);
    gemm16_kernel<0,0><<<dim3(G4 / 256, 64), blk, gemm_smem>>>(h2 + (size_t)(BT / 2) * HH, HH, w16 + W_L2A,
                                                               l2_bih0, l2_bhh0,
                                                               gates + (size_t)(BT / 2) * G4, BT / 2, G4, HH);
    fused_recur_kernel<<<128, blk, fused_smem>>>(gates, l2_Whh0, l2_Wih1, l2_Whh1,
                                                 l2_bih1, l2_bhh1, hlast, h1F, h2F);

    // [6][7][8] MLP on h2(255)
    gemm16_kernel<1,1><<<dim3(HH / 256, 1), blk, gemm_smem>>>(hlast, HH, w16 + W_M1, mlp_b1, nullptr,
                                                              z1, BB, HH, HH);
    gemm16_kernel<1,1><<<dim3((HH / 2) / 256, 1), blk, gemm_smem>>>(z1, HH, w16 + W_M2, mlp_b2, nullptr,
                                                                    z2, BB, HH / 2, HH);
    mlp3_kernel<<<BB, blk>>>(z2, mlp_W3, mlp_b3, out);
}